// round 2
// baseline (speedup 1.0000x reference)
#include <cuda_runtime.h>
#include <cuda_bf16.h>
#include <math.h>

#define BB 2
#define TT 1024
#define MM 1024
#define FF 1024
#define NHEAD 16
#define HH 64
#define SS 2048            // M + T
#define NH 1024            // N * H
#define SCALE 0.125f       // 1/sqrt(64)
#define NEGINF -1e30f

// ---------------- scratch (device globals; no allocation allowed) ----------------
__device__ float         g_kvin[(size_t)BB * SS * FF];     // concat(memory, x)      16 MB
__device__ float         g_qv[(size_t)BB * TT * NH];       // q + v  (fp32)           8 MB
__device__ __nv_bfloat16 g_qu[(size_t)BB * TT * NH];       // bf16(q + u)             4 MB
__device__ __nv_bfloat16 g_kb[(size_t)BB * SS * NH];       // bf16(k)                 8 MB
__device__ __nv_bfloat16 g_vb[(size_t)BB * SS * NH];       // bf16(val)               8 MB
__device__ float         g_r [(size_t)SS * NH];            // r (fp32)                8 MB
__device__ float         g_logits[(size_t)BB * NHEAD * TT * SS]; //                 256 MB
__device__ float         g_rmax[BB * NHEAD * TT];
__device__ float         g_rsum[BB * NHEAD * TT];
__device__ int           g_qi[BB * TT];
__device__ float         g_attn[(size_t)BB * TT * NH];     // fp32(bf16(attn))        8 MB

// ---------------- kv concat: [B,S,F] = [memory ; x] ----------------
__global__ void build_kv(const float* __restrict__ x, const float* __restrict__ mem)
{
    size_t i = (size_t)blockIdx.x * blockDim.x + threadIdx.x;
    const size_t n4 = (size_t)BB * SS * FF / 4;
    if (i >= n4) return;
    size_t e = i * 4;
    int b = (int)(e / ((size_t)SS * FF));
    size_t rem = e - (size_t)b * SS * FF;
    int s = (int)(rem / FF);
    int f = (int)(rem - (size_t)s * FF);
    float4 val;
    if (s < MM) val = *(const float4*)(mem + ((size_t)b * MM + s) * FF + f);
    else        val = *(const float4*)(x   + ((size_t)b * TT + (s - MM)) * FF + f);
    *(float4*)(g_kvin + e) = val;
}

// ---------------- qi[b,t] = episode_idx[b,M-1] + inclusive_cumsum(dones[b])[t] ----------------
__global__ void calc_qi(const int* __restrict__ ep, const int* __restrict__ dones)
{
    __shared__ int sbuf[TT];
    int b = blockIdx.x, t = threadIdx.x;
    sbuf[t] = dones[b * TT + t];
    __syncthreads();
    for (int off = 1; off < TT; off <<= 1) {
        int add = (t >= off) ? sbuf[t - off] : 0;
        __syncthreads();
        sbuf[t] += add;
        __syncthreads();
    }
    g_qi[b * TT + t] = ep[b * MM + (MM - 1)] + sbuf[t];
}

// ---------------- SGEMM 128x128x16, 256 threads, 8x8 microtile ----------------
// C[r][c] = sum_k A[r][k] * W[k][c] ; all matrices have leading dim 1024, K = 1024.
// mode 0: outF = acc + bias1[c] ; outB = bf16(acc + bias2[c])   (q -> q_v, q_u)
// mode 1: outB = bf16(acc)                                       (k, val)
// mode 2: outF = acc                                             (r)
// mode 3: outF = acc + bias1[c]                                  (final output)
__global__ void __launch_bounds__(256) gemm_k(
    const float* __restrict__ A, const float* __restrict__ W, int mode,
    const float* __restrict__ bias1, const float* __restrict__ bias2,
    float* __restrict__ outF, __nv_bfloat16* __restrict__ outB)
{
    __shared__ float As[16][128];
    __shared__ float Bs[16][128];
    const int tid = threadIdx.x;
    const int r0 = blockIdx.y * 128;
    const int c0 = blockIdx.x * 128;
    const int ry = tid >> 4, rx = tid & 15;
    float acc[8][8];
#pragma unroll
    for (int i = 0; i < 8; i++)
#pragma unroll
        for (int j = 0; j < 8; j++) acc[i][j] = 0.f;

    for (int k0 = 0; k0 < FF; k0 += 16) {
#pragma unroll
        for (int l = 0; l < 2; l++) {
            int t = tid + l * 256;
            int r = t >> 2, kq = (t & 3) * 4;
            float4 va = *(const float4*)(A + (size_t)(r0 + r) * FF + k0 + kq);
            As[kq + 0][r] = va.x; As[kq + 1][r] = va.y;
            As[kq + 2][r] = va.z; As[kq + 3][r] = va.w;
            int kb = t >> 5, cq = (t & 31) * 4;
            *(float4*)(&Bs[kb][cq]) = *(const float4*)(W + (size_t)(k0 + kb) * 1024 + c0 + cq);
        }
        __syncthreads();
#pragma unroll
        for (int kk = 0; kk < 16; kk++) {
            float a[8], bv[8];
#pragma unroll
            for (int i = 0; i < 8; i++) a[i] = As[kk][ry * 8 + i];
#pragma unroll
            for (int j = 0; j < 8; j++) bv[j] = Bs[kk][rx * 8 + j];
#pragma unroll
            for (int i = 0; i < 8; i++)
#pragma unroll
                for (int j = 0; j < 8; j++)
                    acc[i][j] = fmaf(a[i], bv[j], acc[i][j]);
        }
        __syncthreads();
    }
#pragma unroll
    for (int i = 0; i < 8; i++) {
        int r = r0 + ry * 8 + i;
#pragma unroll
        for (int j = 0; j < 8; j++) {
            int c = c0 + rx * 8 + j;
            float vacc = acc[i][j];
            size_t o = (size_t)r * 1024 + c;
            if (mode == 0) {
                outF[o] = vacc + bias1[c];
                outB[o] = __float2bfloat16(vacc + bias2[c]);
            } else if (mode == 1) {
                outB[o] = __float2bfloat16(vacc);
            } else if (mode == 2) {
                outF[o] = vacc;
            } else {
                outF[o] = vacc + bias1[c];
            }
        }
    }
}

// ---------------- ATT1: masked logits + online row max/sum ----------------
// logits[b,n,t,s] = f32(bf16(sum_h qu*k)) * scale + (sum_h qv * r[s+T-1-t]) * scale, masked -> -1e30
__global__ void __launch_bounds__(256) att_logits(const int* __restrict__ ep_idx)
{
    extern __shared__ float sm[];
    float* qu_s = sm;                  // 64*65
    float* qv_s = qu_s + 64 * 65;      // 64*65
    float* k_s  = qv_s + 64 * 65;      // 64*65
    float* r_s  = k_s  + 64 * 65;      // 128*65
    int* qi_s = (int*)(r_s + 128 * 65);
    int* ki_s = qi_s + 64;

    const int tid = threadIdx.x;
    const int bn = blockIdx.x;
    const int b = bn >> 4, n = bn & 15;
    const int t0 = blockIdx.y * 64;
    const int ty = tid >> 4, tx = tid & 15;
    const int qbase = ty * 4, sbase = tx * 4;

    for (int e = tid; e < 4096; e += 256) {
        int q = e >> 6, h = e & 63;
        size_t row = (size_t)(b * TT + t0 + q) * NH + n * 64 + h;
        qu_s[q * 65 + h] = __bfloat162float(g_qu[row]);
        qv_s[q * 65 + h] = g_qv[row];
    }
    if (tid < 64) qi_s[tid] = g_qi[b * TT + t0 + tid];

    float rmax[4], rsum[4];
#pragma unroll
    for (int i = 0; i < 4; i++) { rmax[i] = -INFINITY; rsum[i] = 0.f; }

    for (int s0 = 0; s0 < SS; s0 += 64) {
        __syncthreads();
        for (int e = tid; e < 4096; e += 256) {
            int s = e >> 6, h = e & 63;
            k_s[s * 65 + h] = __bfloat162float(g_kb[(size_t)(b * SS + s0 + s) * NH + n * 64 + h]);
        }
        const int base = s0 - t0 + (TT - 64);   // r row for (q_loc=63, s_loc=0)
        for (int e = tid; e < 8192; e += 256) {
            int j = e >> 6, h = e & 63;
            int m = base + j; m = (m > SS - 1) ? SS - 1 : m;  // OOB rows are masked anyway
            r_s[j * 65 + h] = g_r[(size_t)m * NH + n * 64 + h];
        }
        if (tid < 64) {
            int s = s0 + tid;
            ki_s[tid] = (s < MM) ? ep_idx[b * MM + s] : g_qi[b * TT + (s - MM)];
        }
        __syncthreads();

        float qk[4][4], bbx[4][4];
#pragma unroll
        for (int i = 0; i < 4; i++)
#pragma unroll
            for (int j = 0; j < 4; j++) { qk[i][j] = 0.f; bbx[i][j] = 0.f; }
        const int rrow0 = sbase - qbase + 60;   // j - i + 3 offsets into rr[7]
#pragma unroll 4
        for (int h = 0; h < 64; h++) {
            float au[4], av[4], kk4[4], rr[7];
#pragma unroll
            for (int i = 0; i < 4; i++) {
                au[i] = qu_s[(qbase + i) * 65 + h];
                av[i] = qv_s[(qbase + i) * 65 + h];
            }
#pragma unroll
            for (int j = 0; j < 4; j++) kk4[j] = k_s[(sbase + j) * 65 + h];
#pragma unroll
            for (int d = 0; d < 7; d++) rr[d] = r_s[(rrow0 + d) * 65 + h];
#pragma unroll
            for (int i = 0; i < 4; i++)
#pragma unroll
                for (int j = 0; j < 4; j++) {
                    qk[i][j]  = fmaf(au[i], kk4[j], qk[i][j]);
                    bbx[i][j] = fmaf(av[i], rr[j - i + 3], bbx[i][j]);
                }
        }
        float lv[4][4];
#pragma unroll
        for (int i = 0; i < 4; i++) {
            int tg = t0 + qbase + i;
#pragma unroll
            for (int j = 0; j < 4; j++) {
                int sg = s0 + sbase + j;
                // replicate: f32(bf16(qk_dot)) * scale + bias*scale
                float l = __bfloat162float(__float2bfloat16(qk[i][j])) * SCALE + bbx[i][j] * SCALE;
                bool ok = (sg <= MM + tg) && (qi_s[qbase + i] == ki_s[sbase + j]);
                l = ok ? l : NEGINF;
                lv[i][j] = l;
                g_logits[((size_t)bn * TT + tg) * SS + sg] = l;
            }
        }
        // online max/sum per query row, reduced over the 16 tx lanes of this half-warp
#pragma unroll
        for (int i = 0; i < 4; i++) {
            float tm = fmaxf(fmaxf(lv[i][0], lv[i][1]), fmaxf(lv[i][2], lv[i][3]));
#pragma unroll
            for (int msk = 1; msk < 16; msk <<= 1)
                tm = fmaxf(tm, __shfl_xor_sync(0xffffffffu, tm, msk));
            float nm = fmaxf(rmax[i], tm);
            float ps = expf(lv[i][0] - nm) + expf(lv[i][1] - nm) +
                       expf(lv[i][2] - nm) + expf(lv[i][3] - nm);
#pragma unroll
            for (int msk = 1; msk < 16; msk <<= 1)
                ps += __shfl_xor_sync(0xffffffffu, ps, msk);
            rsum[i] = rsum[i] * expf(rmax[i] - nm) + ps;
            rmax[i] = nm;
        }
    }
    if (tx == 0) {
#pragma unroll
        for (int i = 0; i < 4; i++) {
            int tg = t0 + qbase + i;
            g_rmax[bn * TT + tg] = rmax[i];
            g_rsum[bn * TT + tg] = rsum[i];
        }
    }
}

// ---------------- ATT2: probs (bf16-rounded after normalization) @ val ----------------
__global__ void __launch_bounds__(256) att_pv()
{
    __shared__ float p_s[64][65];
    __shared__ float v_s[64][65];
    __shared__ float rm_s[64], rs_s[64];
    const int tid = threadIdx.x;
    const int bn = blockIdx.x;
    const int b = bn >> 4, n = bn & 15;
    const int t0 = blockIdx.y * 64;
    const int ty = tid >> 4, tx = tid & 15;

    if (tid < 64) {
        rm_s[tid] = g_rmax[bn * TT + t0 + tid];
        rs_s[tid] = g_rsum[bn * TT + t0 + tid];
    }
    float acc[4][4];
#pragma unroll
    for (int i = 0; i < 4; i++)
#pragma unroll
        for (int j = 0; j < 4; j++) acc[i][j] = 0.f;

    for (int s0 = 0; s0 < SS; s0 += 64) {
        __syncthreads();
        for (int e = tid; e < 4096; e += 256) {
            int q = e >> 6, s = e & 63;
            float L = g_logits[((size_t)bn * TT + t0 + q) * SS + s0 + s];
            float p = expf(L - rm_s[q]) / rs_s[q];
            p_s[q][s] = __bfloat162float(__float2bfloat16(p));   // exact prob rounding
        }
        for (int e = tid; e < 4096; e += 256) {
            int s = e >> 6, h = e & 63;
            v_s[s][h] = __bfloat162float(g_vb[(size_t)(b * SS + s0 + s) * NH + n * 64 + h]);
        }
        __syncthreads();
#pragma unroll 8
        for (int s = 0; s < 64; s++) {
            float pv[4], vv[4];
#pragma unroll
            for (int i = 0; i < 4; i++) pv[i] = p_s[ty * 4 + i][s];
#pragma unroll
            for (int j = 0; j < 4; j++) vv[j] = v_s[s][tx * 4 + j];
#pragma unroll
            for (int i = 0; i < 4; i++)
#pragma unroll
                for (int j = 0; j < 4; j++)
                    acc[i][j] = fmaf(pv[i], vv[j], acc[i][j]);
        }
    }
#pragma unroll
    for (int i = 0; i < 4; i++) {
        int t = t0 + ty * 4 + i;
#pragma unroll
        for (int j = 0; j < 4; j++) {
            g_attn[(size_t)(b * TT + t) * NH + n * 64 + tx * 4 + j] =
                __bfloat162float(__float2bfloat16(acc[i][j]));   // attn einsum output is bf16
        }
    }
}

// ---------------- launch ----------------
extern "C" void kernel_launch(void* const* d_in, const int* in_sizes, int n_in,
                              void* d_out, int out_size)
{
    const float* x    = (const float*)d_in[0];
    const float* rel  = (const float*)d_in[1];
    const float* mem  = (const float*)d_in[2];
    const int*   ep   = (const int*)d_in[3];
    const int*   dones= (const int*)d_in[4];
    const float* Wq   = (const float*)d_in[5];
    const float* Wk   = (const float*)d_in[6];
    const float* Wv   = (const float*)d_in[7];
    const float* Wr   = (const float*)d_in[8];
    const float* u    = (const float*)d_in[9];
    const float* v    = (const float*)d_in[10];
    const float* Wout = (const float*)d_in[11];
    const float* bo   = (const float*)d_in[12];
    float* out = (float*)d_out;
    (void)in_sizes; (void)n_in; (void)out_size;

    void *pkv, *pqv, *pqu, *pkb, *pvb, *pr, *pattn;
    cudaGetSymbolAddress(&pkv,   g_kvin);
    cudaGetSymbolAddress(&pqv,   g_qv);
    cudaGetSymbolAddress(&pqu,   g_qu);
    cudaGetSymbolAddress(&pkb,   g_kb);
    cudaGetSymbolAddress(&pvb,   g_vb);
    cudaGetSymbolAddress(&pr,    g_r);
    cudaGetSymbolAddress(&pattn, g_attn);

    build_kv<<<(BB * SS * FF / 4 + 255) / 256, 256>>>(x, mem);
    calc_qi<<<BB, TT>>>(ep, dones);

    // projections
    gemm_k<<<dim3(8, 16), 256>>>(x, Wq, 0, v, u, (float*)pqv, (__nv_bfloat16*)pqu);
    gemm_k<<<dim3(8, 32), 256>>>((const float*)pkv, Wk, 1, nullptr, nullptr,
                                 nullptr, (__nv_bfloat16*)pkb);
    gemm_k<<<dim3(8, 32), 256>>>((const float*)pkv, Wv, 1, nullptr, nullptr,
                                 nullptr, (__nv_bfloat16*)pvb);
    gemm_k<<<dim3(8, 16), 256>>>(rel, Wr, 2, nullptr, nullptr, (float*)pr, nullptr);

    // attention
    const int att1_smem = (3 * 64 * 65 + 128 * 65) * (int)sizeof(float) + 128 * (int)sizeof(int);
    cudaFuncSetAttribute(att_logits, cudaFuncAttributeMaxDynamicSharedMemorySize, att1_smem);
    att_logits<<<dim3(BB * NHEAD, TT / 64), 256, att1_smem>>>(ep);
    att_pv<<<dim3(BB * NHEAD, TT / 64), 256>>>();

    // output projection + bias
    gemm_k<<<dim3(8, 16), 256>>>((const float*)pattn, Wout, 3, bo, nullptr, out, nullptr);
}

// round 4
// speedup vs baseline: 1.3302x; 1.3302x over previous
#include <cuda_runtime.h>
#include <cuda_bf16.h>
#include <cstdint>
#include <math.h>

#define BB 2
#define TT 1024
#define MM 1024
#define FF 1024
#define NHEAD 16
#define HH 64
#define SS 2048            // M + T
#define NH 1024            // N * H
#define SCALE 0.125f       // 1/sqrt(64)
#define NEGINF -1e30f

#define KP 3072            // split-emulated K for projections
#define KO 2048            // split-emulated K for output gemm

// ======================= scratch (device globals) =======================
__device__ float         g_qv[(size_t)BB * TT * NH];        // q + v  (fp32)
__device__ __nv_bfloat16 g_qu[(size_t)BB * TT * NH];        // bf16(q + u)
__device__ __nv_bfloat16 g_kb[(size_t)BB * SS * NH];        // bf16(k)
__device__ __nv_bfloat16 g_vb[(size_t)BB * SS * NH];        // bf16(val)
__device__ float         g_r [(size_t)SS * NH];             // r (fp32)
__device__ float         g_logits[(size_t)BB * NHEAD * TT * SS];
__device__ float         g_rmax[BB * NHEAD * TT];
__device__ float         g_rsum[BB * NHEAD * TT];
__device__ int           g_qi[BB * TT];

// split-emulation operand buffers (A' along K' = [a1|a1|a2], B' = [b1|b2|b1])
__device__ __nv_bfloat16 g_xs [(size_t)BB * TT * KP];       // x'      [2048][3072]
__device__ __nv_bfloat16 g_kvs[(size_t)BB * SS * KP];       // kv'     [4096][3072]
__device__ __nv_bfloat16 g_rs [(size_t)SS * KP];            // rel'    [2048][3072]
__device__ __nv_bfloat16 g_wt [5 * (size_t)NH * KP];        // 5 weights, [n][3072]
__device__ __nv_bfloat16 g_attn2[(size_t)BB * TT * KO];     // [attn|attn] [2048][2048]

// ======================= PTX helpers =======================
__device__ __forceinline__ uint32_t smem_to_u32(const void* p) {
    uint32_t a;
    asm("{ .reg .u64 t; cvta.to.shared.u64 t, %1; cvt.u32.u64 %0, t; }" : "=r"(a) : "l"(p));
    return a;
}
__device__ __forceinline__ uint32_t swz(uint32_t byte_off) {
    return byte_off ^ ((byte_off >> 3) & 0x70u);
}
#define CP_ASYNC16(dst, src) \
    asm volatile("cp.async.cg.shared.global [%0], [%1], 16;" :: "r"(dst), "l"(src))
#define CP_COMMIT() asm volatile("cp.async.commit_group;" ::: "memory")
#define CP_WAIT(n)  asm volatile("cp.async.wait_group %0;" :: "n"(n) : "memory")
#define LDSM_X4(r0, r1, r2, r3, addr) \
    asm volatile("ldmatrix.sync.aligned.m8n8.x4.shared.b16 {%0,%1,%2,%3}, [%4];" \
        : "=r"(r0), "=r"(r1), "=r"(r2), "=r"(r3) : "r"(addr))
#define MMA16816(d, a0, a1, a2, a3, b0, b1) \
    asm volatile("mma.sync.aligned.m16n8k16.row.col.f32.bf16.bf16.f32 " \
        "{%0,%1,%2,%3}, {%4,%5,%6,%7}, {%8,%9}, {%0,%1,%2,%3};" \
        : "+f"((d)[0]), "+f"((d)[1]), "+f"((d)[2]), "+f"((d)[3]) \
        : "r"(a0), "r"(a1), "r"(a2), "r"(a3), "r"(b0), "r"(b1))

// ======================= conversion kernels =======================
// fp32 [rows][1024] -> bf16 [rows][3072] = [a1 | a1 | a2]
__global__ void split_dupA(const float* __restrict__ src, __nv_bfloat16* __restrict__ dst, int rows)
{
    int i = blockIdx.x * blockDim.x + threadIdx.x;
    if (i >= rows * 1024) return;
    int r = i >> 10, k = i & 1023;
    float a = src[i];
    __nv_bfloat16 h1 = __float2bfloat16(a);
    __nv_bfloat16 h2 = __float2bfloat16(a - __bfloat162float(h1));
    size_t o = (size_t)r * KP + k;
    dst[o] = h1; dst[o + 1024] = h1; dst[o + 2048] = h2;
}

// concat(memory, x) -> [a1|a1|a2]  layout [b][s][3072]
__global__ void kv_split(const float* __restrict__ x, const float* __restrict__ mem)
{
    size_t i = (size_t)blockIdx.x * blockDim.x + threadIdx.x;
    if (i >= (size_t)BB * SS * FF) return;
    int b = (int)(i / ((size_t)SS * FF));
    size_t rem = i - (size_t)b * SS * FF;
    int s = (int)(rem / FF);
    int f = (int)(rem - (size_t)s * FF);
    float a = (s < MM) ? mem[((size_t)b * MM + s) * FF + f]
                       : x[((size_t)b * TT + (s - MM)) * FF + f];
    __nv_bfloat16 h1 = __float2bfloat16(a);
    __nv_bfloat16 h2 = __float2bfloat16(a - __bfloat162float(h1));
    size_t o = (size_t)(b * SS + s) * KP + f;
    g_kvs[o] = h1; g_kvs[o + 1024] = h1; g_kvs[o + 2048] = h2;
}

// W [1024 k][1024 n] -> Bt [n][ldK]: b1 @ +0, b2 @ +1024, (dup) b1 @ +2048
__global__ void transsplit(const float* __restrict__ W, __nv_bfloat16* __restrict__ o,
                           int ldK, int dup)
{
    __shared__ float t[32][33];
    int k = blockIdx.y * 32 + threadIdx.y;
    int n = blockIdx.x * 32 + threadIdx.x;
    t[threadIdx.y][threadIdx.x] = W[(size_t)k * 1024 + n];
    __syncthreads();
    int nn = blockIdx.x * 32 + threadIdx.y;
    int kk = blockIdx.y * 32 + threadIdx.x;
    float a = t[threadIdx.x][threadIdx.y];
    __nv_bfloat16 h1 = __float2bfloat16(a);
    __nv_bfloat16 h2 = __float2bfloat16(a - __bfloat162float(h1));
    size_t ob = (size_t)nn * ldK + kk;
    o[ob] = h1; o[ob + 1024] = h2;
    if (dup) o[ob + 2048] = h1;
}

// ======================= qi cumsum =======================
__global__ void calc_qi(const int* __restrict__ ep, const int* __restrict__ dones)
{
    __shared__ int sbuf[TT];
    int b = blockIdx.x, t = threadIdx.x;
    sbuf[t] = dones[b * TT + t];
    __syncthreads();
    for (int off = 1; off < TT; off <<= 1) {
        int add = (t >= off) ? sbuf[t - off] : 0;
        __syncthreads();
        sbuf[t] += add;
        __syncthreads();
    }
    g_qi[b * TT + t] = ep[b * MM + (MM - 1)] + sbuf[t];
}

// ======================= HMMA bf16 GEMM (mma.sync m16n8k16) =======================
// C[128x128] per CTA; C[r][c] = sum_k A[r][k] * Bt[c][k]  (fp32 accum).
// 256 threads = 8 warps (2 x 4); warp tile 64 x 32; K-chunk 64, double-buffered cp.async.
// mode 0: outF=acc+bias1[c], outB=bf16(acc+bias2[c]); 1: outB=bf16(acc); 2: outF=acc; 3: outF=acc+bias1[c]
#define HG_STAGE 16384                    // 128 x 64 bf16 bytes
#define HG_SMEM  (4 * HG_STAGE)           // A x2 stages + B x2 stages = 64 KB

__global__ void __launch_bounds__(256, 1) hmma_gemm(
    const __nv_bfloat16* __restrict__ A, int ldA,
    const __nv_bfloat16* __restrict__ Bt, int ldB, int K,
    int mode, const float* __restrict__ bias1, const float* __restrict__ bias2,
    float* __restrict__ outF, __nv_bfloat16* __restrict__ outB)
{
    extern __shared__ char smem[];
    const uint32_t sA = smem_to_u32(smem);
    const uint32_t sB = sA + 2 * HG_STAGE;
    const int tid = threadIdx.x;
    const int lane = tid & 31, warp = tid >> 5;
    const int wm = warp >> 2, wn = warp & 3;          // 2 x 4 warp grid
    const int r0 = blockIdx.y * 128, c0 = blockIdx.x * 128;

    float acc[4][4][4];
#pragma unroll
    for (int mt = 0; mt < 4; mt++)
#pragma unroll
        for (int nt = 0; nt < 4; nt++)
#pragma unroll
            for (int e = 0; e < 4; e++) acc[mt][nt][e] = 0.f;

    auto load_stage = [&](int stage, int k0) {
        uint32_t ab = sA + stage * HG_STAGE;
        uint32_t bb = sB + stage * HG_STAGE;
#pragma unroll
        for (int it = 0; it < 8; it++) {
            int idx = tid + it * 256;                 // 0..2047
            int row = (idx >> 3) & 127, seg = idx & 7;
            uint32_t off = swz((uint32_t)(row * 128 + seg * 16));
            if (idx < 1024) {
                const __nv_bfloat16* src = A + (size_t)(r0 + row) * ldA + k0 + seg * 8;
                CP_ASYNC16(ab + off, src);
            } else {
                const __nv_bfloat16* src = Bt + (size_t)(c0 + row) * ldB + k0 + seg * 8;
                CP_ASYNC16(bb + off, src);
            }
        }
    };

    const int lrow = lane & 15;
    const uint32_t col8 = (lane >> 4) * 8;

    auto compute = [&](int stage) {
        uint32_t ab = sA + stage * HG_STAGE;
        uint32_t bb = sB + stage * HG_STAGE;
#pragma unroll
        for (int kk = 0; kk < 4; kk++) {
            uint32_t af[4][4], bfr[2][4];
#pragma unroll
            for (int mt = 0; mt < 4; mt++) {
                uint32_t addr = ab + swz((uint32_t)((wm * 64 + mt * 16 + lrow) * 128 +
                                                    (kk * 16 + col8) * 2));
                LDSM_X4(af[mt][0], af[mt][1], af[mt][2], af[mt][3], addr);
            }
#pragma unroll
            for (int bt = 0; bt < 2; bt++) {
                uint32_t addr = bb + swz((uint32_t)((wn * 32 + bt * 16 + lrow) * 128 +
                                                    (kk * 16 + col8) * 2));
                LDSM_X4(bfr[bt][0], bfr[bt][1], bfr[bt][2], bfr[bt][3], addr);
            }
#pragma unroll
            for (int mt = 0; mt < 4; mt++)
#pragma unroll
                for (int bt = 0; bt < 2; bt++) {
                    MMA16816(acc[mt][2 * bt],     af[mt][0], af[mt][1], af[mt][2], af[mt][3],
                             bfr[bt][0], bfr[bt][2]);
                    MMA16816(acc[mt][2 * bt + 1], af[mt][0], af[mt][1], af[mt][2], af[mt][3],
                             bfr[bt][1], bfr[bt][3]);
                }
        }
    };

    const int nchunks = K >> 6;
    load_stage(0, 0);
    CP_COMMIT();
    for (int c = 0; c < nchunks; c++) {
        if (c + 1 < nchunks) {
            load_stage((c + 1) & 1, (c + 1) * 64);
            CP_COMMIT();
            CP_WAIT(1);
        } else {
            CP_WAIT(0);
        }
        __syncthreads();
        compute(c & 1);
        __syncthreads();
    }

    // ---- epilogue ----
#pragma unroll
    for (int mt = 0; mt < 4; mt++) {
        int rbase = r0 + wm * 64 + mt * 16 + (lane >> 2);
#pragma unroll
        for (int nt = 0; nt < 4; nt++) {
            int cbase = c0 + wn * 32 + nt * 8 + (lane & 3) * 2;
#pragma unroll
            for (int e = 0; e < 4; e++) {
                int r = rbase + (e >> 1) * 8;
                int c = cbase + (e & 1);
                float vv = acc[mt][nt][e];
                size_t o = (size_t)r * 1024 + c;
                if (mode == 0) {
                    outF[o] = vv + bias1[c];
                    outB[o] = __float2bfloat16(vv + bias2[c]);
                } else if (mode == 1) {
                    outB[o] = __float2bfloat16(vv);
                } else if (mode == 2) {
                    outF[o] = vv;
                } else {
                    outF[o] = vv + bias1[c];
                }
            }
        }
    }
}

// ======================= ATT1: masked logits + online row max/sum =======================
__global__ void __launch_bounds__(256) att_logits(const int* __restrict__ ep_idx)
{
    extern __shared__ float sm[];
    float* qu_s = sm;
    float* qv_s = qu_s + 64 * 65;
    float* k_s  = qv_s + 64 * 65;
    float* r_s  = k_s  + 64 * 65;
    int* qi_s = (int*)(r_s + 128 * 65);
    int* ki_s = qi_s + 64;

    const int tid = threadIdx.x;
    const int bn = blockIdx.x;
    const int b = bn >> 4, n = bn & 15;
    const int t0 = blockIdx.y * 64;
    const int ty = tid >> 4, tx = tid & 15;
    const int qbase = ty * 4, sbase = tx * 4;

    for (int e = tid; e < 4096; e += 256) {
        int q = e >> 6, h = e & 63;
        size_t row = (size_t)(b * TT + t0 + q) * NH + n * 64 + h;
        qu_s[q * 65 + h] = __bfloat162float(g_qu[row]);
        qv_s[q * 65 + h] = g_qv[row];
    }
    if (tid < 64) qi_s[tid] = g_qi[b * TT + t0 + tid];

    float rmax[4], rsum[4];
#pragma unroll
    for (int i = 0; i < 4; i++) { rmax[i] = -INFINITY; rsum[i] = 0.f; }

    for (int s0 = 0; s0 < SS; s0 += 64) {
        __syncthreads();
        for (int e = tid; e < 4096; e += 256) {
            int s = e >> 6, h = e & 63;
            k_s[s * 65 + h] = __bfloat162float(g_kb[(size_t)(b * SS + s0 + s) * NH + n * 64 + h]);
        }
        const int base = s0 - t0 + (TT - 64);
        for (int e = tid; e < 8192; e += 256) {
            int j = e >> 6, h = e & 63;
            int m = base + j; m = (m > SS - 1) ? SS - 1 : m;
            r_s[j * 65 + h] = g_r[(size_t)m * NH + n * 64 + h];
        }
        if (tid < 64) {
            int s = s0 + tid;
            ki_s[tid] = (s < MM) ? ep_idx[b * MM + s] : g_qi[b * TT + (s - MM)];
        }
        __syncthreads();

        float qk[4][4], bbx[4][4];
#pragma unroll
        for (int i = 0; i < 4; i++)
#pragma unroll
            for (int j = 0; j < 4; j++) { qk[i][j] = 0.f; bbx[i][j] = 0.f; }
        const int rrow0 = sbase - qbase + 60;
#pragma unroll 4
        for (int h = 0; h < 64; h++) {
            float au[4], av[4], kk4[4], rr[7];
#pragma unroll
            for (int i = 0; i < 4; i++) {
                au[i] = qu_s[(qbase + i) * 65 + h];
                av[i] = qv_s[(qbase + i) * 65 + h];
            }
#pragma unroll
            for (int j = 0; j < 4; j++) kk4[j] = k_s[(sbase + j) * 65 + h];
#pragma unroll
            for (int d = 0; d < 7; d++) rr[d] = r_s[(rrow0 + d) * 65 + h];
#pragma unroll
            for (int i = 0; i < 4; i++)
#pragma unroll
                for (int j = 0; j < 4; j++) {
                    qk[i][j]  = fmaf(au[i], kk4[j], qk[i][j]);
                    bbx[i][j] = fmaf(av[i], rr[j - i + 3], bbx[i][j]);
                }
        }
        float lv[4][4];
#pragma unroll
        for (int i = 0; i < 4; i++) {
            int tg = t0 + qbase + i;
#pragma unroll
            for (int j = 0; j < 4; j++) {
                int sg = s0 + sbase + j;
                float l = __bfloat162float(__float2bfloat16(qk[i][j])) * SCALE + bbx[i][j] * SCALE;
                bool ok = (sg <= MM + tg) && (qi_s[qbase + i] == ki_s[sbase + j]);
                l = ok ? l : NEGINF;
                lv[i][j] = l;
                g_logits[((size_t)bn * TT + tg) * SS + sg] = l;
            }
        }
#pragma unroll
        for (int i = 0; i < 4; i++) {
            float tm = fmaxf(fmaxf(lv[i][0], lv[i][1]), fmaxf(lv[i][2], lv[i][3]));
#pragma unroll
            for (int msk = 1; msk < 16; msk <<= 1)
                tm = fmaxf(tm, __shfl_xor_sync(0xffffffffu, tm, msk));
            float nm = fmaxf(rmax[i], tm);
            float ps = expf(lv[i][0] - nm) + expf(lv[i][1] - nm) +
                       expf(lv[i][2] - nm) + expf(lv[i][3] - nm);
#pragma unroll
            for (int msk = 1; msk < 16; msk <<= 1)
                ps += __shfl_xor_sync(0xffffffffu, ps, msk);
            rsum[i] = rsum[i] * expf(rmax[i] - nm) + ps;
            rmax[i] = nm;
        }
    }
    if (tx == 0) {
#pragma unroll
        for (int i = 0; i < 4; i++) {
            int tg = t0 + qbase + i;
            g_rmax[bn * TT + tg] = rmax[i];
            g_rsum[bn * TT + tg] = rsum[i];
        }
    }
}

// ======================= ATT2: probs (bf16 after normalization) @ val =======================
__global__ void __launch_bounds__(256) att_pv()
{
    __shared__ float p_s[64][65];
    __shared__ float v_s[64][65];
    __shared__ float rm_s[64], rs_s[64];
    const int tid = threadIdx.x;
    const int bn = blockIdx.x;
    const int b = bn >> 4, n = bn & 15;
    const int t0 = blockIdx.y * 64;
    const int ty = tid >> 4, tx = tid & 15;

    if (tid < 64) {
        rm_s[tid] = g_rmax[bn * TT + t0 + tid];
        rs_s[tid] = g_rsum[bn * TT + t0 + tid];
    }
    float acc[4][4];
#pragma unroll
    for (int i = 0; i < 4; i++)
#pragma unroll
        for (int j = 0; j < 4; j++) acc[i][j] = 0.f;

    for (int s0 = 0; s0 < SS; s0 += 64) {
        __syncthreads();
        for (int e = tid; e < 4096; e += 256) {
            int q = e >> 6, s = e & 63;
            float L = g_logits[((size_t)bn * TT + t0 + q) * SS + s0 + s];
            float p = expf(L - rm_s[q]) / rs_s[q];
            p_s[q][s] = __bfloat162float(__float2bfloat16(p));
        }
        for (int e = tid; e < 4096; e += 256) {
            int s = e >> 6, h = e & 63;
            v_s[s][h] = __bfloat162float(g_vb[(size_t)(b * SS + s0 + s) * NH + n * 64 + h]);
        }
        __syncthreads();
#pragma unroll 8
        for (int s = 0; s < 64; s++) {
            float pv[4], vv[4];
#pragma unroll
            for (int i = 0; i < 4; i++) pv[i] = p_s[ty * 4 + i][s];
#pragma unroll
            for (int j = 0; j < 4; j++) vv[j] = v_s[s][tx * 4 + j];
#pragma unroll
            for (int i = 0; i < 4; i++)
#pragma unroll
                for (int j = 0; j < 4; j++)
                    acc[i][j] = fmaf(pv[i], vv[j], acc[i][j]);
        }
    }
#pragma unroll
    for (int i = 0; i < 4; i++) {
        int t = t0 + ty * 4 + i;
#pragma unroll
        for (int j = 0; j < 4; j++) {
            __nv_bfloat16 h = __float2bfloat16(acc[i][j]);  // exact ref bf16 attn
            size_t o = (size_t)(b * TT + t) * KO + n * 64 + tx * 4 + j;
            g_attn2[o] = h;            // [attn | attn] duplicated along K'
            g_attn2[o + 1024] = h;
        }
    }
}

// ======================= launch =======================
extern "C" void kernel_launch(void* const* d_in, const int* in_sizes, int n_in,
                              void* d_out, int out_size)
{
    const float* x    = (const float*)d_in[0];
    const float* rel  = (const float*)d_in[1];
    const float* mem  = (const float*)d_in[2];
    const int*   ep   = (const int*)d_in[3];
    const int*   dones= (const int*)d_in[4];
    const float* Wq   = (const float*)d_in[5];
    const float* Wk   = (const float*)d_in[6];
    const float* Wv   = (const float*)d_in[7];
    const float* Wr   = (const float*)d_in[8];
    const float* u    = (const float*)d_in[9];
    const float* v    = (const float*)d_in[10];
    const float* Wout = (const float*)d_in[11];
    const float* bo   = (const float*)d_in[12];
    float* out = (float*)d_out;
    (void)in_sizes; (void)n_in; (void)out_size;

    void *pqv, *pqu, *pkb, *pvb, *pr, *pxs, *pkvs, *prs, *pwt, *pattn2;
    cudaGetSymbolAddress(&pqv,    g_qv);
    cudaGetSymbolAddress(&pqu,    g_qu);
    cudaGetSymbolAddress(&pkb,    g_kb);
    cudaGetSymbolAddress(&pvb,    g_vb);
    cudaGetSymbolAddress(&pr,     g_r);
    cudaGetSymbolAddress(&pxs,    g_xs);
    cudaGetSymbolAddress(&pkvs,   g_kvs);
    cudaGetSymbolAddress(&prs,    g_rs);
    cudaGetSymbolAddress(&pwt,    g_wt);
    cudaGetSymbolAddress(&pattn2, g_attn2);

    __nv_bfloat16* xs  = (__nv_bfloat16*)pxs;
    __nv_bfloat16* kvs = (__nv_bfloat16*)pkvs;
    __nv_bfloat16* rs  = (__nv_bfloat16*)prs;
    __nv_bfloat16* wt  = (__nv_bfloat16*)pwt;
    const size_t WSTRIDE = (size_t)NH * KP;   // per-weight stride

    // ---- conversions ----
    split_dupA<<<(BB * TT * FF + 255) / 256, 256>>>(x, xs, BB * TT);
    kv_split<<<(int)(((size_t)BB * SS * FF + 255) / 256), 256>>>(x, mem);
    split_dupA<<<(SS * FF + 255) / 256, 256>>>(rel, rs, SS);
    const float* Ws[5] = { Wq, Wk, Wv, Wr, Wout };
    for (int w = 0; w < 5; w++)
        transsplit<<<dim3(32, 32), dim3(32, 32)>>>(Ws[w], wt + (size_t)w * WSTRIDE,
                                                   KP, (w < 4) ? 1 : 0);
    calc_qi<<<BB, TT>>>(ep, dones);

    // ---- HMMA GEMMs ----
    cudaFuncSetAttribute(hmma_gemm, cudaFuncAttributeMaxDynamicSharedMemorySize, HG_SMEM);
    __nv_bfloat16 *wq = wt, *wk = wt + WSTRIDE, *wv = wt + 2 * WSTRIDE,
                  *wr = wt + 3 * WSTRIDE, *wo = wt + 4 * WSTRIDE;

    // q: [2048 x 1024]: q_v (fp32, +v) and q_u (bf16, +u)
    hmma_gemm<<<dim3(8, 16), 256, HG_SMEM>>>(xs, KP, wq, KP, KP, 0, v, u,
                                             (float*)pqv, (__nv_bfloat16*)pqu);
    // k: [4096 x 1024] -> bf16
    hmma_gemm<<<dim3(8, 32), 256, HG_SMEM>>>(kvs, KP, wk, KP, KP, 1, nullptr, nullptr,
                                             nullptr, (__nv_bfloat16*)pkb);
    // val: [4096 x 1024] -> bf16
    hmma_gemm<<<dim3(8, 32), 256, HG_SMEM>>>(kvs, KP, wv, KP, KP, 1, nullptr, nullptr,
                                             nullptr, (__nv_bfloat16*)pvb);
    // r: [2048 x 1024] -> fp32
    hmma_gemm<<<dim3(8, 16), 256, HG_SMEM>>>(rs, KP, wr, KP, KP, 2, nullptr, nullptr,
                                             (float*)pr, nullptr);

    // ---- attention ----
    const int att1_smem = (3 * 64 * 65 + 128 * 65) * (int)sizeof(float) + 128 * (int)sizeof(int);
    cudaFuncSetAttribute(att_logits, cudaFuncAttributeMaxDynamicSharedMemorySize, att1_smem);
    att_logits<<<dim3(BB * NHEAD, TT / 64), 256, att1_smem>>>(ep);
    att_pv<<<dim3(BB * NHEAD, TT / 64), 256>>>();

    // ---- output projection: [attn|attn] @ [b1|b2] + b_out ----
    hmma_gemm<<<dim3(8, 16), 256, HG_SMEM>>>((__nv_bfloat16*)pattn2, KO, wo, KP, KO,
                                             3, bo, nullptr, out, nullptr);
}

// round 5
// speedup vs baseline: 4.4997x; 3.3828x over previous
#include <cuda_runtime.h>
#include <cuda_bf16.h>
#include <cstdint>
#include <math.h>

#define BB 2
#define TT 1024
#define MM 1024
#define FF 1024
#define NHEAD 16
#define HH 64
#define SS 2048            // M + T
#define NH 1024            // N * H
#define SCALE 0.125f       // 1/sqrt(64)
#define NEGINF -1e30f

#define KP 3072            // split-emulated K for projections
#define KO 2048            // split-emulated K for output gemm

// ======================= scratch (device globals) =======================
__device__ float         g_qv[(size_t)BB * TT * NH];        // q + v  (fp32)
__device__ __nv_bfloat16 g_qu[(size_t)BB * TT * NH];        // bf16(q + u)
__device__ __nv_bfloat16 g_kb[(size_t)BB * SS * NH];        // bf16(k)
__device__ __nv_bfloat16 g_vb[(size_t)BB * SS * NH];        // bf16(val)
__device__ float         g_r [(size_t)SS * NH];             // r (fp32)
__device__ float         g_logits[(size_t)BB * NHEAD * TT * SS];
__device__ float         g_rmax[BB * NHEAD * TT];
__device__ float         g_rsum[BB * NHEAD * TT];
__device__ int           g_qi[BB * TT];
__device__ int           g_ki[BB * SS];

// split-emulation operand buffers (A' along K' = [a1|a1|a2], B' = [b1|b2|b1])
__device__ __nv_bfloat16 g_xs [(size_t)BB * TT * KP];       // x'      [2048][3072]
__device__ __nv_bfloat16 g_kvs[(size_t)BB * SS * KP];       // kv'     [4096][3072]
__device__ __nv_bfloat16 g_rs [(size_t)SS * KP];            // rel'    [2048][3072]
__device__ __nv_bfloat16 g_wt [5 * (size_t)NH * KP];        // 5 weights, [n][3072]
__device__ __nv_bfloat16 g_attn2[(size_t)BB * TT * KO];     // [attn|attn] [2048][2048]

// ======================= PTX helpers =======================
__device__ __forceinline__ uint32_t smem_to_u32(const void* p) {
    uint32_t a;
    asm("{ .reg .u64 t; cvta.to.shared.u64 t, %1; cvt.u32.u64 %0, t; }" : "=r"(a) : "l"(p));
    return a;
}
__device__ __forceinline__ uint32_t swz(uint32_t byte_off) {
    return byte_off ^ ((byte_off >> 3) & 0x70u);
}
#define CP_ASYNC16(dst, src) \
    asm volatile("cp.async.cg.shared.global [%0], [%1], 16;" :: "r"(dst), "l"(src))
#define CP_COMMIT() asm volatile("cp.async.commit_group;" ::: "memory")
#define CP_WAIT(n)  asm volatile("cp.async.wait_group %0;" :: "n"(n) : "memory")
#define LDSM_X4(r0, r1, r2, r3, addr) \
    asm volatile("ldmatrix.sync.aligned.m8n8.x4.shared.b16 {%0,%1,%2,%3}, [%4];" \
        : "=r"(r0), "=r"(r1), "=r"(r2), "=r"(r3) : "r"(addr))
#define MMA16816(d, a0, a1, a2, a3, b0, b1) \
    asm volatile("mma.sync.aligned.m16n8k16.row.col.f32.bf16.bf16.f32 " \
        "{%0,%1,%2,%3}, {%4,%5,%6,%7}, {%8,%9}, {%0,%1,%2,%3};" \
        : "+f"((d)[0]), "+f"((d)[1]), "+f"((d)[2]), "+f"((d)[3]) \
        : "r"(a0), "r"(a1), "r"(a2), "r"(a3), "r"(b0), "r"(b1))

// ======================= conversion kernels =======================
// fp32 [rows][1024] -> bf16 [rows][3072] = [a1 | a1 | a2]
__global__ void split_dupA(const float* __restrict__ src, __nv_bfloat16* __restrict__ dst, int rows)
{
    int i = blockIdx.x * blockDim.x + threadIdx.x;
    if (i >= rows * 1024) return;
    int r = i >> 10, k = i & 1023;
    float a = src[i];
    __nv_bfloat16 h1 = __float2bfloat16(a);
    __nv_bfloat16 h2 = __float2bfloat16(a - __bfloat162float(h1));
    size_t o = (size_t)r * KP + k;
    dst[o] = h1; dst[o + 1024] = h1; dst[o + 2048] = h2;
}

// concat(memory, x) -> [a1|a1|a2]  layout [b][s][3072]
__global__ void kv_split(const float* __restrict__ x, const float* __restrict__ mem)
{
    size_t i = (size_t)blockIdx.x * blockDim.x + threadIdx.x;
    if (i >= (size_t)BB * SS * FF) return;
    int b = (int)(i / ((size_t)SS * FF));
    size_t rem = i - (size_t)b * SS * FF;
    int s = (int)(rem / FF);
    int f = (int)(rem - (size_t)s * FF);
    float a = (s < MM) ? mem[((size_t)b * MM + s) * FF + f]
                       : x[((size_t)b * TT + (s - MM)) * FF + f];
    __nv_bfloat16 h1 = __float2bfloat16(a);
    __nv_bfloat16 h2 = __float2bfloat16(a - __bfloat162float(h1));
    size_t o = (size_t)(b * SS + s) * KP + f;
    g_kvs[o] = h1; g_kvs[o + 1024] = h1; g_kvs[o + 2048] = h2;
}

// W [1024 k][1024 n] -> Bt [n][ldK]: b1 @ +0, b2 @ +1024, (dup) b1 @ +2048
__global__ void transsplit(const float* __restrict__ W, __nv_bfloat16* __restrict__ o,
                           int ldK, int dup)
{
    __shared__ float t[32][33];
    int k = blockIdx.y * 32 + threadIdx.y;
    int n = blockIdx.x * 32 + threadIdx.x;
    t[threadIdx.y][threadIdx.x] = W[(size_t)k * 1024 + n];
    __syncthreads();
    int nn = blockIdx.x * 32 + threadIdx.y;
    int kk = blockIdx.y * 32 + threadIdx.x;
    float a = t[threadIdx.x][threadIdx.y];
    __nv_bfloat16 h1 = __float2bfloat16(a);
    __nv_bfloat16 h2 = __float2bfloat16(a - __bfloat162float(h1));
    size_t ob = (size_t)nn * ldK + kk;
    o[ob] = h1; o[ob + 1024] = h2;
    if (dup) o[ob + 2048] = h1;
}

// ======================= qi cumsum + ki array =======================
__global__ void calc_qi(const int* __restrict__ ep, const int* __restrict__ dones)
{
    __shared__ int sbuf[TT];
    int b = blockIdx.x, t = threadIdx.x;
    sbuf[t] = dones[b * TT + t];
    __syncthreads();
    for (int off = 1; off < TT; off <<= 1) {
        int add = (t >= off) ? sbuf[t - off] : 0;
        __syncthreads();
        sbuf[t] += add;
        __syncthreads();
    }
    int q = ep[b * MM + (MM - 1)] + sbuf[t];
    g_qi[b * TT + t] = q;
    g_ki[b * SS + MM + t] = q;          // x-part keys
    g_ki[b * SS + t] = ep[b * MM + t];  // memory-part keys (TT == MM)
}

// ======================= HMMA bf16 GEMM (mma.sync m16n8k16) =======================
// C[128x128] per CTA; C[r][c] = sum_k A[r][k] * Bt[c][k]  (fp32 accum).
// 256 threads = 8 warps (2 x 4); warp tile 64 x 32; K-chunk 64, double-buffered cp.async.
// mode 0: outF=acc+bias1[c], outB=bf16(acc+bias2[c]); 1: outB=bf16(acc); 2: outF=acc; 3: outF=acc+bias1[c]
#define HG_STAGE 16384                    // 128 x 64 bf16 bytes
#define HG_SMEM  (4 * HG_STAGE)           // A x2 stages + B x2 stages = 64 KB

__global__ void __launch_bounds__(256, 1) hmma_gemm(
    const __nv_bfloat16* __restrict__ A, int ldA,
    const __nv_bfloat16* __restrict__ Bt, int ldB, int K,
    int mode, const float* __restrict__ bias1, const float* __restrict__ bias2,
    float* __restrict__ outF, __nv_bfloat16* __restrict__ outB)
{
    extern __shared__ char smem[];
    const uint32_t sA = smem_to_u32(smem);
    const uint32_t sB = sA + 2 * HG_STAGE;
    const int tid = threadIdx.x;
    const int lane = tid & 31, warp = tid >> 5;
    const int wm = warp >> 2, wn = warp & 3;          // 2 x 4 warp grid
    const int r0 = blockIdx.y * 128, c0 = blockIdx.x * 128;

    float acc[4][4][4];
#pragma unroll
    for (int mt = 0; mt < 4; mt++)
#pragma unroll
        for (int nt = 0; nt < 4; nt++)
#pragma unroll
            for (int e = 0; e < 4; e++) acc[mt][nt][e] = 0.f;

    auto load_stage = [&](int stage, int k0) {
        uint32_t ab = sA + stage * HG_STAGE;
        uint32_t bb = sB + stage * HG_STAGE;
#pragma unroll
        for (int it = 0; it < 8; it++) {
            int idx = tid + it * 256;                 // 0..2047
            int row = (idx >> 3) & 127, seg = idx & 7;
            uint32_t off = swz((uint32_t)(row * 128 + seg * 16));
            if (idx < 1024) {
                const __nv_bfloat16* src = A + (size_t)(r0 + row) * ldA + k0 + seg * 8;
                CP_ASYNC16(ab + off, src);
            } else {
                const __nv_bfloat16* src = Bt + (size_t)(c0 + row) * ldB + k0 + seg * 8;
                CP_ASYNC16(bb + off, src);
            }
        }
    };

    const int lrow = lane & 15;
    const uint32_t col8 = (lane >> 4) * 8;

    auto compute = [&](int stage) {
        uint32_t ab = sA + stage * HG_STAGE;
        uint32_t bb = sB + stage * HG_STAGE;
#pragma unroll
        for (int kk = 0; kk < 4; kk++) {
            uint32_t af[4][4], bfr[2][4];
#pragma unroll
            for (int mt = 0; mt < 4; mt++) {
                uint32_t addr = ab + swz((uint32_t)((wm * 64 + mt * 16 + lrow) * 128 +
                                                    (kk * 16 + col8) * 2));
                LDSM_X4(af[mt][0], af[mt][1], af[mt][2], af[mt][3], addr);
            }
#pragma unroll
            for (int bt = 0; bt < 2; bt++) {
                uint32_t addr = bb + swz((uint32_t)((wn * 32 + bt * 16 + lrow) * 128 +
                                                    (kk * 16 + col8) * 2));
                LDSM_X4(bfr[bt][0], bfr[bt][1], bfr[bt][2], bfr[bt][3], addr);
            }
#pragma unroll
            for (int mt = 0; mt < 4; mt++)
#pragma unroll
                for (int bt = 0; bt < 2; bt++) {
                    MMA16816(acc[mt][2 * bt],     af[mt][0], af[mt][1], af[mt][2], af[mt][3],
                             bfr[bt][0], bfr[bt][2]);
                    MMA16816(acc[mt][2 * bt + 1], af[mt][0], af[mt][1], af[mt][2], af[mt][3],
                             bfr[bt][1], bfr[bt][3]);
                }
        }
    };

    const int nchunks = K >> 6;
    load_stage(0, 0);
    CP_COMMIT();
    for (int c = 0; c < nchunks; c++) {
        if (c + 1 < nchunks) {
            load_stage((c + 1) & 1, (c + 1) * 64);
            CP_COMMIT();
            CP_WAIT(1);
        } else {
            CP_WAIT(0);
        }
        __syncthreads();
        compute(c & 1);
        __syncthreads();
    }

    // ---- epilogue ----
#pragma unroll
    for (int mt = 0; mt < 4; mt++) {
        int rbase = r0 + wm * 64 + mt * 16 + (lane >> 2);
#pragma unroll
        for (int nt = 0; nt < 4; nt++) {
            int cbase = c0 + wn * 32 + nt * 8 + (lane & 3) * 2;
#pragma unroll
            for (int e = 0; e < 4; e++) {
                int r = rbase + (e >> 1) * 8;
                int c = cbase + (e & 1);
                float vv = acc[mt][nt][e];
                size_t o = (size_t)r * 1024 + c;
                if (mode == 0) {
                    outF[o] = vv + bias1[c];
                    outB[o] = __float2bfloat16(vv + bias2[c]);
                } else if (mode == 1) {
                    outB[o] = __float2bfloat16(vv);
                } else if (mode == 2) {
                    outF[o] = vv;
                } else {
                    outF[o] = vv + bias1[c];
                }
            }
        }
    }
}

// ======================= ATT1: masked logits + online row max/sum =======================
// Tile-skip: for a 64x64 (t,s) tile, if the episode-index bands don't overlap or the
// whole tile is causally masked, every logit is NEG -> exp == 0 exactly -> skip is exact.
__global__ void __launch_bounds__(256) att_logits(const int* __restrict__ ep_idx)
{
    extern __shared__ float sm[];
    float* qu_s = sm;
    float* qv_s = qu_s + 64 * 65;
    float* k_s  = qv_s + 64 * 65;
    float* r_s  = k_s  + 64 * 65;
    int* qi_s = (int*)(r_s + 128 * 65);
    int* ki_s = qi_s + 64;

    const int tid = threadIdx.x;
    const int bn = blockIdx.x;
    const int b = bn >> 4, n = bn & 15;
    const int t0 = blockIdx.y * 64;
    const int ty = tid >> 4, tx = tid & 15;
    const int qbase = ty * 4, sbase = tx * 4;

    for (int e = tid; e < 4096; e += 256) {
        int q = e >> 6, h = e & 63;
        size_t row = (size_t)(b * TT + t0 + q) * NH + n * 64 + h;
        qu_s[q * 65 + h] = __bfloat162float(g_qu[row]);
        qv_s[q * 65 + h] = g_qv[row];
    }
    if (tid < 64) qi_s[tid] = g_qi[b * TT + t0 + tid];
    __syncthreads();

    const int qlo = qi_s[0], qhi = qi_s[63];       // qi nondecreasing in t
    const int causal_max = MM + t0 + 63;

    float rmax[4], rsum[4];
#pragma unroll
    for (int i = 0; i < 4; i++) { rmax[i] = -INFINITY; rsum[i] = 0.f; }

    for (int s0 = 0; s0 < SS; s0 += 64) {
        if (s0 > causal_max) break;                 // all later tiles fully causal-masked
        {   // episode band test (ki nondecreasing in s); uniform across block
            int klo = g_ki[b * SS + s0];
            int khi = g_ki[b * SS + s0 + 63];
            if (khi < qlo || klo > qhi) continue;   // fully masked tile -> exact zero contribution
        }
        __syncthreads();
        for (int e = tid; e < 4096; e += 256) {
            int s = e >> 6, h = e & 63;
            k_s[s * 65 + h] = __bfloat162float(g_kb[(size_t)(b * SS + s0 + s) * NH + n * 64 + h]);
        }
        const int base = s0 - t0 + (TT - 64);
        for (int e = tid; e < 8192; e += 256) {
            int j = e >> 6, h = e & 63;
            int m = base + j; m = (m > SS - 1) ? SS - 1 : m; m = (m < 0) ? 0 : m;
            r_s[j * 65 + h] = g_r[(size_t)m * NH + n * 64 + h];
        }
        if (tid < 64) {
            int s = s0 + tid;
            ki_s[tid] = (s < MM) ? ep_idx[b * MM + s] : g_qi[b * TT + (s - MM)];
        }
        __syncthreads();

        float qk[4][4], bbx[4][4];
#pragma unroll
        for (int i = 0; i < 4; i++)
#pragma unroll
            for (int j = 0; j < 4; j++) { qk[i][j] = 0.f; bbx[i][j] = 0.f; }
        const int rrow0 = sbase - qbase + 60;
#pragma unroll 4
        for (int h = 0; h < 64; h++) {
            float au[4], av[4], kk4[4], rr[7];
#pragma unroll
            for (int i = 0; i < 4; i++) {
                au[i] = qu_s[(qbase + i) * 65 + h];
                av[i] = qv_s[(qbase + i) * 65 + h];
            }
#pragma unroll
            for (int j = 0; j < 4; j++) kk4[j] = k_s[(sbase + j) * 65 + h];
#pragma unroll
            for (int d = 0; d < 7; d++) rr[d] = r_s[(rrow0 + d) * 65 + h];
#pragma unroll
            for (int i = 0; i < 4; i++)
#pragma unroll
                for (int j = 0; j < 4; j++) {
                    qk[i][j]  = fmaf(au[i], kk4[j], qk[i][j]);
                    bbx[i][j] = fmaf(av[i], rr[j - i + 3], bbx[i][j]);
                }
        }
        float lv[4][4];
#pragma unroll
        for (int i = 0; i < 4; i++) {
            int tg = t0 + qbase + i;
#pragma unroll
            for (int j = 0; j < 4; j++) {
                int sg = s0 + sbase + j;
                float l = __bfloat162float(__float2bfloat16(qk[i][j])) * SCALE + bbx[i][j] * SCALE;
                bool ok = (sg <= MM + tg) && (qi_s[qbase + i] == ki_s[sbase + j]);
                l = ok ? l : NEGINF;
                lv[i][j] = l;
                g_logits[((size_t)bn * TT + tg) * SS + sg] = l;
            }
        }
#pragma unroll
        for (int i = 0; i < 4; i++) {
            float tm = fmaxf(fmaxf(lv[i][0], lv[i][1]), fmaxf(lv[i][2], lv[i][3]));
#pragma unroll
            for (int msk = 1; msk < 16; msk <<= 1)
                tm = fmaxf(tm, __shfl_xor_sync(0xffffffffu, tm, msk));
            float nm = fmaxf(rmax[i], tm);
            float ps = expf(lv[i][0] - nm) + expf(lv[i][1] - nm) +
                       expf(lv[i][2] - nm) + expf(lv[i][3] - nm);
#pragma unroll
            for (int msk = 1; msk < 16; msk <<= 1)
                ps += __shfl_xor_sync(0xffffffffu, ps, msk);
            rsum[i] = rsum[i] * expf(rmax[i] - nm) + ps;
            rmax[i] = nm;
        }
    }
    if (tx == 0) {
#pragma unroll
        for (int i = 0; i < 4; i++) {
            int tg = t0 + qbase + i;
            g_rmax[bn * TT + tg] = rmax[i];
            g_rsum[bn * TT + tg] = rsum[i];
        }
    }
}

// ======================= ATT2: probs (bf16 after normalization) @ val =======================
__global__ void __launch_bounds__(256) att_pv()
{
    __shared__ float p_s[64][65];
    __shared__ float v_s[64][65];
    __shared__ float rm_s[64], rs_s[64];
    const int tid = threadIdx.x;
    const int bn = blockIdx.x;
    const int b = bn >> 4, n = bn & 15;
    const int t0 = blockIdx.y * 64;
    const int ty = tid >> 4, tx = tid & 15;

    if (tid < 64) {
        rm_s[tid] = g_rmax[bn * TT + t0 + tid];
        rs_s[tid] = g_rsum[bn * TT + t0 + tid];
    }
    const int qlo = g_qi[b * TT + t0];
    const int qhi = g_qi[b * TT + t0 + 63];
    const int causal_max = MM + t0 + 63;

    float acc[4][4];
#pragma unroll
    for (int i = 0; i < 4; i++)
#pragma unroll
        for (int j = 0; j < 4; j++) acc[i][j] = 0.f;

    for (int s0 = 0; s0 < SS; s0 += 64) {
        if (s0 > causal_max) break;
        {
            int klo = g_ki[b * SS + s0];
            int khi = g_ki[b * SS + s0 + 63];
            if (khi < qlo || klo > qhi) continue;   // exp(NEG - max) == 0 exactly
        }
        __syncthreads();
        for (int e = tid; e < 4096; e += 256) {
            int q = e >> 6, s = e & 63;
            float L = g_logits[((size_t)bn * TT + t0 + q) * SS + s0 + s];
            float p = expf(L - rm_s[q]) / rs_s[q];
            p_s[q][s] = __bfloat162float(__float2bfloat16(p));
        }
        for (int e = tid; e < 4096; e += 256) {
            int s = e >> 6, h = e & 63;
            v_s[s][h] = __bfloat162float(g_vb[(size_t)(b * SS + s0 + s) * NH + n * 64 + h]);
        }
        __syncthreads();
#pragma unroll 8
        for (int s = 0; s < 64; s++) {
            float pv[4], vv[4];
#pragma unroll
            for (int i = 0; i < 4; i++) pv[i] = p_s[ty * 4 + i][s];
#pragma unroll
            for (int j = 0; j < 4; j++) vv[j] = v_s[s][tx * 4 + j];
#pragma unroll
            for (int i = 0; i < 4; i++)
#pragma unroll
                for (int j = 0; j < 4; j++)
                    acc[i][j] = fmaf(pv[i], vv[j], acc[i][j]);
        }
    }
#pragma unroll
    for (int i = 0; i < 4; i++) {
        int t = t0 + ty * 4 + i;
#pragma unroll
        for (int j = 0; j < 4; j++) {
            __nv_bfloat16 h = __float2bfloat16(acc[i][j]);  // exact ref bf16 attn
            size_t o = (size_t)(b * TT + t) * KO + n * 64 + tx * 4 + j;
            g_attn2[o] = h;            // [attn | attn] duplicated along K'
            g_attn2[o + 1024] = h;
        }
    }
}

// ======================= launch =======================
extern "C" void kernel_launch(void* const* d_in, const int* in_sizes, int n_in,
                              void* d_out, int out_size)
{
    const float* x    = (const float*)d_in[0];
    const float* rel  = (const float*)d_in[1];
    const float* mem  = (const float*)d_in[2];
    const int*   ep   = (const int*)d_in[3];
    const int*   dones= (const int*)d_in[4];
    const float* Wq   = (const float*)d_in[5];
    const float* Wk   = (const float*)d_in[6];
    const float* Wv   = (const float*)d_in[7];
    const float* Wr   = (const float*)d_in[8];
    const float* u    = (const float*)d_in[9];
    const float* v    = (const float*)d_in[10];
    const float* Wout = (const float*)d_in[11];
    const float* bo   = (const float*)d_in[12];
    float* out = (float*)d_out;
    (void)in_sizes; (void)n_in; (void)out_size;

    void *pqv, *pqu, *pkb, *pvb, *pr, *pxs, *pkvs, *prs, *pwt, *pattn2;
    cudaGetSymbolAddress(&pqv,    g_qv);
    cudaGetSymbolAddress(&pqu,    g_qu);
    cudaGetSymbolAddress(&pkb,    g_kb);
    cudaGetSymbolAddress(&pvb,    g_vb);
    cudaGetSymbolAddress(&pr,     g_r);
    cudaGetSymbolAddress(&pxs,    g_xs);
    cudaGetSymbolAddress(&pkvs,   g_kvs);
    cudaGetSymbolAddress(&prs,    g_rs);
    cudaGetSymbolAddress(&pwt,    g_wt);
    cudaGetSymbolAddress(&pattn2, g_attn2);

    __nv_bfloat16* xs  = (__nv_bfloat16*)pxs;
    __nv_bfloat16* kvs = (__nv_bfloat16*)pkvs;
    __nv_bfloat16* rs  = (__nv_bfloat16*)prs;
    __nv_bfloat16* wt  = (__nv_bfloat16*)pwt;
    const size_t WSTRIDE = (size_t)NH * KP;   // per-weight stride

    // ---- conversions ----
    split_dupA<<<(BB * TT * FF + 255) / 256, 256>>>(x, xs, BB * TT);
    kv_split<<<(int)(((size_t)BB * SS * FF + 255) / 256), 256>>>(x, mem);
    split_dupA<<<(SS * FF + 255) / 256, 256>>>(rel, rs, SS);
    const float* Ws[5] = { Wq, Wk, Wv, Wr, Wout };
    for (int w = 0; w < 5; w++)
        transsplit<<<dim3(32, 32), dim3(32, 32)>>>(Ws[w], wt + (size_t)w * WSTRIDE,
                                                   KP, (w < 4) ? 1 : 0);
    calc_qi<<<BB, TT>>>(ep, dones);

    // ---- HMMA GEMMs ----
    cudaFuncSetAttribute(hmma_gemm, cudaFuncAttributeMaxDynamicSharedMemorySize, HG_SMEM);
    __nv_bfloat16 *wq = wt, *wk = wt + WSTRIDE, *wv = wt + 2 * WSTRIDE,
                  *wr = wt + 3 * WSTRIDE, *wo = wt + 4 * WSTRIDE;

    // q: [2048 x 1024]: q_v (fp32, +v) and q_u (bf16, +u)
    hmma_gemm<<<dim3(8, 16), 256, HG_SMEM>>>(xs, KP, wq, KP, KP, 0, v, u,
                                             (float*)pqv, (__nv_bfloat16*)pqu);
    // k: [4096 x 1024] -> bf16
    hmma_gemm<<<dim3(8, 32), 256, HG_SMEM>>>(kvs, KP, wk, KP, KP, 1, nullptr, nullptr,
                                             nullptr, (__nv_bfloat16*)pkb);
    // val: [4096 x 1024] -> bf16
    hmma_gemm<<<dim3(8, 32), 256, HG_SMEM>>>(kvs, KP, wv, KP, KP, 1, nullptr, nullptr,
                                             nullptr, (__nv_bfloat16*)pvb);
    // r: [2048 x 1024] -> fp32
    hmma_gemm<<<dim3(8, 16), 256, HG_SMEM>>>(rs, KP, wr, KP, KP, 2, nullptr, nullptr,
                                             (float*)pr, nullptr);

    // ---- attention (tile-skipped) ----
    const int att1_smem = (3 * 64 * 65 + 128 * 65) * (int)sizeof(float) + 128 * (int)sizeof(int);
    cudaFuncSetAttribute(att_logits, cudaFuncAttributeMaxDynamicSharedMemorySize, att1_smem);
    att_logits<<<dim3(BB * NHEAD, TT / 64), 256, att1_smem>>>(ep);
    att_pv<<<dim3(BB * NHEAD, TT / 64), 256>>>();

    // ---- output projection: [attn|attn] @ [b1|b2] + b_out ----
    hmma_gemm<<<dim3(8, 16), 256, HG_SMEM>>>((__nv_bfloat16*)pattn2, KO, wo, KP, KO,
                                             3, bo, nullptr, out, nullptr);
}

// round 6
// speedup vs baseline: 4.6308x; 1.0291x over previous
#include <cuda_runtime.h>
#include <cuda_bf16.h>
#include <cstdint>
#include <math.h>

#define BB 2
#define TT 1024
#define MM 1024
#define FF 1024
#define NHEAD 16
#define HH 64
#define SS 2048            // M + T
#define NH 1024            // N * H
#define SCALE 0.125f       // 1/sqrt(64)
#define NEGINF -1e30f

#define KP 3072            // split-emulated K for projections
#define KO 2048            // split-emulated K for output gemm

// ======================= scratch (device globals) =======================
__device__ float         g_qv[(size_t)BB * TT * NH];        // q + v  (fp32)
__device__ __nv_bfloat16 g_qu[(size_t)BB * TT * NH];        // bf16(q + u)
__device__ __nv_bfloat16 g_kb[(size_t)BB * SS * NH];        // bf16(k)
__device__ __nv_bfloat16 g_vb[(size_t)BB * SS * NH];        // bf16(val)
__device__ float         g_r [(size_t)SS * NH];             // r (fp32)
__device__ float         g_logits[(size_t)BB * NHEAD * TT * SS];
__device__ float         g_rmax[BB * NHEAD * TT];
__device__ float         g_rsum[BB * NHEAD * TT];
__device__ int           g_qi[BB * TT];
__device__ int           g_ki[BB * SS];

// split-emulation operand buffers (A' along K' = [a1|a1|a2], B' = [b1|b2|b1])
__device__ __nv_bfloat16 g_kvs[(size_t)BB * SS * KP];       // kv'   [4096][3072] (x rows embedded)
__device__ __nv_bfloat16 g_rs [(size_t)SS * KP];            // rel'  [2048][3072]
__device__ __nv_bfloat16 g_wt [5 * (size_t)NH * KP];        // 5 weights, [n][3072]
__device__ __nv_bfloat16 g_attn2[(size_t)BB * TT * KO];     // [attn|attn] [2048][2048]

// ======================= PTX helpers =======================
__device__ __forceinline__ uint32_t smem_to_u32(const void* p) {
    uint32_t a;
    asm("{ .reg .u64 t; cvta.to.shared.u64 t, %1; cvt.u32.u64 %0, t; }" : "=r"(a) : "l"(p));
    return a;
}
__device__ __forceinline__ uint32_t swz(uint32_t byte_off) {
    return byte_off ^ ((byte_off >> 3) & 0x70u);
}
#define CP_ASYNC16(dst, src) \
    asm volatile("cp.async.cg.shared.global [%0], [%1], 16;" :: "r"(dst), "l"(src))
#define CP_COMMIT() asm volatile("cp.async.commit_group;" ::: "memory")
#define CP_WAIT(n)  asm volatile("cp.async.wait_group %0;" :: "n"(n) : "memory")
#define LDSM_X4(r0, r1, r2, r3, addr) \
    asm volatile("ldmatrix.sync.aligned.m8n8.x4.shared.b16 {%0,%1,%2,%3}, [%4];" \
        : "=r"(r0), "=r"(r1), "=r"(r2), "=r"(r3) : "r"(addr))
#define MMA16816(d, a0, a1, a2, a3, b0, b1) \
    asm volatile("mma.sync.aligned.m16n8k16.row.col.f32.bf16.bf16.f32 " \
        "{%0,%1,%2,%3}, {%4,%5,%6,%7}, {%8,%9}, {%0,%1,%2,%3};" \
        : "+f"((d)[0]), "+f"((d)[1]), "+f"((d)[2]), "+f"((d)[3]) \
        : "r"(a0), "r"(a1), "r"(a2), "r"(a3), "r"(b0), "r"(b1))

// ======================= conversion kernels =======================
// fp32 [rows][1024] -> bf16 [rows][3072] = [a1 | a1 | a2]  (used for rel only)
__global__ void split_dupA(const float* __restrict__ src, __nv_bfloat16* __restrict__ dst, int rows)
{
    int i = blockIdx.x * blockDim.x + threadIdx.x;
    if (i >= rows * 1024) return;
    int r = i >> 10, k = i & 1023;
    float a = src[i];
    __nv_bfloat16 h1 = __float2bfloat16(a);
    __nv_bfloat16 h2 = __float2bfloat16(a - __bfloat162float(h1));
    size_t o = (size_t)r * KP + k;
    dst[o] = h1; dst[o + 1024] = h1; dst[o + 2048] = h2;
}

// concat(memory, x) -> [a1|a1|a2]  layout [b][s][3072]
__global__ void kv_split(const float* __restrict__ x, const float* __restrict__ mem)
{
    size_t i = (size_t)blockIdx.x * blockDim.x + threadIdx.x;
    if (i >= (size_t)BB * SS * FF) return;
    int b = (int)(i / ((size_t)SS * FF));
    size_t rem = i - (size_t)b * SS * FF;
    int s = (int)(rem / FF);
    int f = (int)(rem - (size_t)s * FF);
    float a = (s < MM) ? mem[((size_t)b * MM + s) * FF + f]
                       : x[((size_t)b * TT + (s - MM)) * FF + f];
    __nv_bfloat16 h1 = __float2bfloat16(a);
    __nv_bfloat16 h2 = __float2bfloat16(a - __bfloat162float(h1));
    size_t o = (size_t)(b * SS + s) * KP + f;
    g_kvs[o] = h1; g_kvs[o + 1024] = h1; g_kvs[o + 2048] = h2;
}

// All 5 weights in one launch (z selects weight). W [1024 k][1024 n] -> Bt [n][3072]
__global__ void transsplit5(const float* __restrict__ W0, const float* __restrict__ W1,
                            const float* __restrict__ W2, const float* __restrict__ W3,
                            const float* __restrict__ W4)
{
    __shared__ float t[32][33];
    const float* Ws[5] = { W0, W1, W2, W3, W4 };
    const float* W = Ws[blockIdx.z];
    __nv_bfloat16* o = g_wt + (size_t)blockIdx.z * NH * KP;
    int dup = (blockIdx.z < 4);
    int k = blockIdx.y * 32 + threadIdx.y;
    int n = blockIdx.x * 32 + threadIdx.x;
    t[threadIdx.y][threadIdx.x] = W[(size_t)k * 1024 + n];
    __syncthreads();
    int nn = blockIdx.x * 32 + threadIdx.y;
    int kk = blockIdx.y * 32 + threadIdx.x;
    float a = t[threadIdx.x][threadIdx.y];
    __nv_bfloat16 h1 = __float2bfloat16(a);
    __nv_bfloat16 h2 = __float2bfloat16(a - __bfloat162float(h1));
    size_t ob = (size_t)nn * KP + kk;
    o[ob] = h1; o[ob + 1024] = h2;
    if (dup) o[ob + 2048] = h1;
}

// ======================= qi cumsum + ki array =======================
__global__ void calc_qi(const int* __restrict__ ep, const int* __restrict__ dones)
{
    __shared__ int sbuf[TT];
    int b = blockIdx.x, t = threadIdx.x;
    sbuf[t] = dones[b * TT + t];
    __syncthreads();
    for (int off = 1; off < TT; off <<= 1) {
        int add = (t >= off) ? sbuf[t - off] : 0;
        __syncthreads();
        sbuf[t] += add;
        __syncthreads();
    }
    int q = ep[b * MM + (MM - 1)] + sbuf[t];
    g_qi[b * TT + t] = q;
    g_ki[b * SS + MM + t] = q;          // x-part keys
    g_ki[b * SS + t] = ep[b * MM + t];  // memory-part keys (TT == MM)
}

// ======================= shared HMMA tile machinery =======================
#define HG_STAGE 16384                    // 128 x 64 bf16 bytes
#define HG_SMEM  (4 * HG_STAGE)           // A x2 stages + B x2 stages = 64 KB

struct HmmaCore {
    uint32_t sA, sB;
    int tid, lane, warp, wm, wn, lrow;
    uint32_t col8;
    float acc[4][4][4];

    __device__ __forceinline__ void init(char* smem) {
        sA = smem_to_u32(smem);
        sB = sA + 2 * HG_STAGE;
        tid = threadIdx.x; lane = tid & 31; warp = tid >> 5;
        wm = warp >> 2; wn = warp & 3;
        lrow = lane & 15; col8 = (lane >> 4) * 8;
#pragma unroll
        for (int mt = 0; mt < 4; mt++)
#pragma unroll
            for (int nt = 0; nt < 4; nt++)
#pragma unroll
                for (int e = 0; e < 4; e++) acc[mt][nt][e] = 0.f;
    }
    // Atile: points at first row of this CTA's 128-row A tile; Btile same for B.
    __device__ __forceinline__ void load_stage(int stage, int k0,
            const __nv_bfloat16* __restrict__ Atile, int ldA,
            const __nv_bfloat16* __restrict__ Btile, int ldB) {
        uint32_t ab = sA + stage * HG_STAGE;
        uint32_t bb = sB + stage * HG_STAGE;
#pragma unroll
        for (int it = 0; it < 8; it++) {
            int idx = tid + it * 256;
            int row = (idx >> 3) & 127, seg = idx & 7;
            uint32_t off = swz((uint32_t)(row * 128 + seg * 16));
            if (idx < 1024) CP_ASYNC16(ab + off, Atile + (size_t)row * ldA + k0 + seg * 8);
            else            CP_ASYNC16(bb + off, Btile + (size_t)row * ldB + k0 + seg * 8);
        }
    }
    __device__ __forceinline__ void compute(int stage) {
        uint32_t ab = sA + stage * HG_STAGE;
        uint32_t bb = sB + stage * HG_STAGE;
#pragma unroll
        for (int kk = 0; kk < 4; kk++) {
            uint32_t af[4][4], bfr[2][4];
#pragma unroll
            for (int mt = 0; mt < 4; mt++) {
                uint32_t addr = ab + swz((uint32_t)((wm * 64 + mt * 16 + lrow) * 128 +
                                                    (kk * 16 + col8) * 2));
                LDSM_X4(af[mt][0], af[mt][1], af[mt][2], af[mt][3], addr);
            }
#pragma unroll
            for (int bt = 0; bt < 2; bt++) {
                uint32_t addr = bb + swz((uint32_t)((wn * 32 + bt * 16 + lrow) * 128 +
                                                    (kk * 16 + col8) * 2));
                LDSM_X4(bfr[bt][0], bfr[bt][1], bfr[bt][2], bfr[bt][3], addr);
            }
#pragma unroll
            for (int mt = 0; mt < 4; mt++)
#pragma unroll
                for (int bt = 0; bt < 2; bt++) {
                    MMA16816(acc[mt][2 * bt],     af[mt][0], af[mt][1], af[mt][2], af[mt][3],
                             bfr[bt][0], bfr[bt][2]);
                    MMA16816(acc[mt][2 * bt + 1], af[mt][0], af[mt][1], af[mt][2], af[mt][3],
                             bfr[bt][1], bfr[bt][3]);
                }
        }
    }
    __device__ __forceinline__ void run(const __nv_bfloat16* Atile, int ldA,
                                        const __nv_bfloat16* Btile, int ldB, int K) {
        const int nchunks = K >> 6;
        load_stage(0, 0, Atile, ldA, Btile, ldB);
        CP_COMMIT();
        for (int c = 0; c < nchunks; c++) {
            if (c + 1 < nchunks) {
                load_stage((c + 1) & 1, (c + 1) * 64, Atile, ldA, Btile, ldB);
                CP_COMMIT();
                CP_WAIT(1);
            } else {
                CP_WAIT(0);
            }
            __syncthreads();
            compute(c & 1);
            __syncthreads();
        }
    }
};

// ======================= merged projection GEMM (q, k, v, r in one launch) =======================
// grid = (8, 96): y 0..15 -> q (rows 0..2047, A remapped into g_kvs x-rows)
//                 y 16..47 -> k (rows 0..4095 of g_kvs)
//                 y 48..79 -> v
//                 y 80..95 -> r (g_rs)
__global__ void __launch_bounds__(256, 1) proj_gemm(
    const float* __restrict__ bias_v, const float* __restrict__ bias_u)
{
    extern __shared__ char smem[];
    const int gy = blockIdx.y;
    const int c0 = blockIdx.x * 128;
    const size_t WS = (size_t)NH * KP;

    int gid, rt;
    if      (gy < 16) { gid = 0; rt = gy; }
    else if (gy < 48) { gid = 1; rt = gy - 16; }
    else if (gy < 80) { gid = 2; rt = gy - 48; }
    else              { gid = 3; rt = gy - 80; }
    const int r0 = rt * 128;

    const __nv_bfloat16* Atile;
    if (gid == 0) {                 // q: x rows live inside g_kvs at [b*2048+1024 + t]
        int b = r0 >> 10;
        Atile = g_kvs + (size_t)(b * SS + MM + (r0 & 1023)) * KP;
    } else if (gid == 3) {
        Atile = g_rs + (size_t)r0 * KP;
    } else {
        Atile = g_kvs + (size_t)r0 * KP;
    }
    const __nv_bfloat16* Btile = g_wt + (size_t)gid * WS + (size_t)c0 * KP;

    HmmaCore h;
    h.init(smem);
    h.run(Atile, KP, Btile, KP, KP);

    // ---- epilogue ----
#pragma unroll
    for (int mt = 0; mt < 4; mt++) {
        int rbase = r0 + h.wm * 64 + mt * 16 + (h.lane >> 2);
#pragma unroll
        for (int nt = 0; nt < 4; nt++) {
            int cbase = c0 + h.wn * 32 + nt * 8 + (h.lane & 3) * 2;
#pragma unroll
            for (int e = 0; e < 4; e++) {
                int r = rbase + (e >> 1) * 8;
                int c = cbase + (e & 1);
                float vv = h.acc[mt][nt][e];
                size_t o = (size_t)r * 1024 + c;
                if (gid == 0) {
                    g_qv[o] = vv + bias_v[c];
                    g_qu[o] = __float2bfloat16(vv + bias_u[c]);
                } else if (gid == 1) {
                    g_kb[o] = __float2bfloat16(vv);
                } else if (gid == 2) {
                    g_vb[o] = __float2bfloat16(vv);
                } else {
                    g_r[o] = vv;
                }
            }
        }
    }
}

// ======================= output GEMM: [attn|attn] @ [b1|b2] + b_out =======================
__global__ void __launch_bounds__(256, 1) out_gemm(const float* __restrict__ bo,
                                                   float* __restrict__ out)
{
    extern __shared__ char smem[];
    const int r0 = blockIdx.y * 128, c0 = blockIdx.x * 128;
    const __nv_bfloat16* Atile = g_attn2 + (size_t)r0 * KO;
    const __nv_bfloat16* Btile = g_wt + 4 * (size_t)NH * KP + (size_t)c0 * KP;

    HmmaCore h;
    h.init(smem);
    h.run(Atile, KO, Btile, KP, KO);

#pragma unroll
    for (int mt = 0; mt < 4; mt++) {
        int rbase = r0 + h.wm * 64 + mt * 16 + (h.lane >> 2);
#pragma unroll
        for (int nt = 0; nt < 4; nt++) {
            int cbase = c0 + h.wn * 32 + nt * 8 + (h.lane & 3) * 2;
#pragma unroll
            for (int e = 0; e < 4; e++) {
                int r = rbase + (e >> 1) * 8;
                int c = cbase + (e & 1);
                out[(size_t)r * 1024 + c] = h.acc[mt][nt][e] + bo[c];
            }
        }
    }
}

// ======================= ATT1: masked logits + online row max/sum =======================
__global__ void __launch_bounds__(256) att_logits(const int* __restrict__ ep_idx)
{
    extern __shared__ float sm[];
    float* qu_s = sm;
    float* qv_s = qu_s + 64 * 65;
    float* k_s  = qv_s + 64 * 65;
    float* r_s  = k_s  + 64 * 65;
    int* qi_s = (int*)(r_s + 128 * 65);
    int* ki_s = qi_s + 64;

    const int tid = threadIdx.x;
    const int bn = blockIdx.x;
    const int b = bn >> 4, n = bn & 15;
    const int t0 = blockIdx.y * 64;
    const int ty = tid >> 4, tx = tid & 15;
    const int qbase = ty * 4, sbase = tx * 4;

    for (int e = tid; e < 4096; e += 256) {
        int q = e >> 6, h = e & 63;
        size_t row = (size_t)(b * TT + t0 + q) * NH + n * 64 + h;
        qu_s[q * 65 + h] = __bfloat162float(g_qu[row]);
        qv_s[q * 65 + h] = g_qv[row];
    }
    if (tid < 64) qi_s[tid] = g_qi[b * TT + t0 + tid];
    __syncthreads();

    const int qlo = qi_s[0], qhi = qi_s[63];       // qi nondecreasing in t
    const int causal_max = MM + t0 + 63;

    float rmax[4], rsum[4];
#pragma unroll
    for (int i = 0; i < 4; i++) { rmax[i] = -INFINITY; rsum[i] = 0.f; }

    for (int s0 = 0; s0 < SS; s0 += 64) {
        if (s0 > causal_max) break;
        {
            int klo = g_ki[b * SS + s0];
            int khi = g_ki[b * SS + s0 + 63];
            if (khi < qlo || klo > qhi) continue;   // fully masked tile -> exact zero contribution
        }
        __syncthreads();
        for (int e = tid; e < 4096; e += 256) {
            int s = e >> 6, h = e & 63;
            k_s[s * 65 + h] = __bfloat162float(g_kb[(size_t)(b * SS + s0 + s) * NH + n * 64 + h]);
        }
        const int base = s0 - t0 + (TT - 64);
        for (int e = tid; e < 8192; e += 256) {
            int j = e >> 6, h = e & 63;
            int m = base + j; m = (m > SS - 1) ? SS - 1 : m; m = (m < 0) ? 0 : m;
            r_s[j * 65 + h] = g_r[(size_t)m * NH + n * 64 + h];
        }
        if (tid < 64) {
            int s = s0 + tid;
            ki_s[tid] = (s < MM) ? ep_idx[b * MM + s] : g_qi[b * TT + (s - MM)];
        }
        __syncthreads();

        float qk[4][4], bbx[4][4];
#pragma unroll
        for (int i = 0; i < 4; i++)
#pragma unroll
            for (int j = 0; j < 4; j++) { qk[i][j] = 0.f; bbx[i][j] = 0.f; }
        const int rrow0 = sbase - qbase + 60;
#pragma unroll 4
        for (int h = 0; h < 64; h++) {
            float au[4], av[4], kk4[4], rr[7];
#pragma unroll
            for (int i = 0; i < 4; i++) {
                au[i] = qu_s[(qbase + i) * 65 + h];
                av[i] = qv_s[(qbase + i) * 65 + h];
            }
#pragma unroll
            for (int j = 0; j < 4; j++) kk4[j] = k_s[(sbase + j) * 65 + h];
#pragma unroll
            for (int d = 0; d < 7; d++) rr[d] = r_s[(rrow0 + d) * 65 + h];
#pragma unroll
            for (int i = 0; i < 4; i++)
#pragma unroll
                for (int j = 0; j < 4; j++) {
                    qk[i][j]  = fmaf(au[i], kk4[j], qk[i][j]);
                    bbx[i][j] = fmaf(av[i], rr[j - i + 3], bbx[i][j]);
                }
        }
        float lv[4][4];
#pragma unroll
        for (int i = 0; i < 4; i++) {
            int tg = t0 + qbase + i;
#pragma unroll
            for (int j = 0; j < 4; j++) {
                int sg = s0 + sbase + j;
                float l = __bfloat162float(__float2bfloat16(qk[i][j])) * SCALE + bbx[i][j] * SCALE;
                bool ok = (sg <= MM + tg) && (qi_s[qbase + i] == ki_s[sbase + j]);
                l = ok ? l : NEGINF;
                lv[i][j] = l;
                g_logits[((size_t)bn * TT + tg) * SS + sg] = l;
            }
        }
#pragma unroll
        for (int i = 0; i < 4; i++) {
            float tm = fmaxf(fmaxf(lv[i][0], lv[i][1]), fmaxf(lv[i][2], lv[i][3]));
#pragma unroll
            for (int msk = 1; msk < 16; msk <<= 1)
                tm = fmaxf(tm, __shfl_xor_sync(0xffffffffu, tm, msk));
            float nm = fmaxf(rmax[i], tm);
            float ps = expf(lv[i][0] - nm) + expf(lv[i][1] - nm) +
                       expf(lv[i][2] - nm) + expf(lv[i][3] - nm);
#pragma unroll
            for (int msk = 1; msk < 16; msk <<= 1)
                ps += __shfl_xor_sync(0xffffffffu, ps, msk);
            rsum[i] = rsum[i] * expf(rmax[i] - nm) + ps;
            rmax[i] = nm;
        }
    }
    if (tx == 0) {
#pragma unroll
        for (int i = 0; i < 4; i++) {
            int tg = t0 + qbase + i;
            g_rmax[bn * TT + tg] = rmax[i];
            g_rsum[bn * TT + tg] = rsum[i];
        }
    }
}

// ======================= ATT2: probs (bf16 after normalization) @ val =======================
__global__ void __launch_bounds__(256) att_pv()
{
    __shared__ float p_s[64][65];
    __shared__ float v_s[64][65];
    __shared__ float rm_s[64], rs_s[64];
    const int tid = threadIdx.x;
    const int bn = blockIdx.x;
    const int b = bn >> 4, n = bn & 15;
    const int t0 = blockIdx.y * 64;
    const int ty = tid >> 4, tx = tid & 15;

    if (tid < 64) {
        rm_s[tid] = g_rmax[bn * TT + t0 + tid];
        rs_s[tid] = g_rsum[bn * TT + t0 + tid];
    }
    const int qlo = g_qi[b * TT + t0];
    const int qhi = g_qi[b * TT + t0 + 63];
    const int causal_max = MM + t0 + 63;

    float acc[4][4];
#pragma unroll
    for (int i = 0; i < 4; i++)
#pragma unroll
        for (int j = 0; j < 4; j++) acc[i][j] = 0.f;

    for (int s0 = 0; s0 < SS; s0 += 64) {
        if (s0 > causal_max) break;
        {
            int klo = g_ki[b * SS + s0];
            int khi = g_ki[b * SS + s0 + 63];
            if (khi < qlo || klo > qhi) continue;   // exp(NEG - max) == 0 exactly
        }
        __syncthreads();
        for (int e = tid; e < 4096; e += 256) {
            int q = e >> 6, s = e & 63;
            float L = g_logits[((size_t)bn * TT + t0 + q) * SS + s0 + s];
            float p = expf(L - rm_s[q]) / rs_s[q];
            p_s[q][s] = __bfloat162float(__float2bfloat16(p));
        }
        for (int e = tid; e < 4096; e += 256) {
            int s = e >> 6, h = e & 63;
            v_s[s][h] = __bfloat162float(g_vb[(size_t)(b * SS + s0 + s) * NH + n * 64 + h]);
        }
        __syncthreads();
#pragma unroll 8
        for (int s = 0; s < 64; s++) {
            float pv[4], vv[4];
#pragma unroll
            for (int i = 0; i < 4; i++) pv[i] = p_s[ty * 4 + i][s];
#pragma unroll
            for (int j = 0; j < 4; j++) vv[j] = v_s[s][tx * 4 + j];
#pragma unroll
            for (int i = 0; i < 4; i++)
#pragma unroll
                for (int j = 0; j < 4; j++)
                    acc[i][j] = fmaf(pv[i], vv[j], acc[i][j]);
        }
    }
#pragma unroll
    for (int i = 0; i < 4; i++) {
        int t = t0 + ty * 4 + i;
#pragma unroll
        for (int j = 0; j < 4; j++) {
            __nv_bfloat16 h = __float2bfloat16(acc[i][j]);  // exact ref bf16 attn
            size_t o = (size_t)(b * TT + t) * KO + n * 64 + tx * 4 + j;
            g_attn2[o] = h;            // [attn | attn] duplicated along K'
            g_attn2[o + 1024] = h;
        }
    }
}

// ======================= launch =======================
extern "C" void kernel_launch(void* const* d_in, const int* in_sizes, int n_in,
                              void* d_out, int out_size)
{
    const float* x    = (const float*)d_in[0];
    const float* rel  = (const float*)d_in[1];
    const float* mem  = (const float*)d_in[2];
    const int*   ep   = (const int*)d_in[3];
    const int*   dones= (const int*)d_in[4];
    const float* Wq   = (const float*)d_in[5];
    const float* Wk   = (const float*)d_in[6];
    const float* Wv   = (const float*)d_in[7];
    const float* Wr   = (const float*)d_in[8];
    const float* u    = (const float*)d_in[9];
    const float* v    = (const float*)d_in[10];
    const float* Wout = (const float*)d_in[11];
    const float* bo   = (const float*)d_in[12];
    float* out = (float*)d_out;
    (void)in_sizes; (void)n_in; (void)out_size;

    void* prs;
    cudaGetSymbolAddress(&prs, g_rs);
    __nv_bfloat16* rs = (__nv_bfloat16*)prs;

    // ---- conversions ----
    kv_split<<<(int)(((size_t)BB * SS * FF + 255) / 256), 256>>>(x, mem);
    split_dupA<<<(SS * FF + 255) / 256, 256>>>(rel, rs, SS);
    transsplit5<<<dim3(32, 32, 5), dim3(32, 32)>>>(Wq, Wk, Wv, Wr, Wout);
    calc_qi<<<BB, TT>>>(ep, dones);

    // ---- merged projection GEMMs (q, k, v, r) ----
    cudaFuncSetAttribute(proj_gemm, cudaFuncAttributeMaxDynamicSharedMemorySize, HG_SMEM);
    proj_gemm<<<dim3(8, 96), 256, HG_SMEM>>>(v, u);

    // ---- attention (tile-skipped) ----
    const int att1_smem = (3 * 64 * 65 + 128 * 65) * (int)sizeof(float) + 128 * (int)sizeof(int);
    cudaFuncSetAttribute(att_logits, cudaFuncAttributeMaxDynamicSharedMemorySize, att1_smem);
    att_logits<<<dim3(BB * NHEAD, TT / 64), 256, att1_smem>>>(ep);
    att_pv<<<dim3(BB * NHEAD, TT / 64), 256>>>();

    // ---- output projection ----
    cudaFuncSetAttribute(out_gemm, cudaFuncAttributeMaxDynamicSharedMemorySize, HG_SMEM);
    out_gemm<<<dim3(8, 16), 256, HG_SMEM>>>(bo, out);
}

// round 7
// speedup vs baseline: 4.9978x; 1.0793x over previous
#include <cuda_runtime.h>
#include <cuda_bf16.h>
#include <cstdint>
#include <math.h>

#define BB 2
#define TT 1024
#define MM 1024
#define FF 1024
#define NHEAD 16
#define HH 64
#define SS 2048            // M + T
#define NH 1024            // N * H
#define SCALE 0.125f       // 1/sqrt(64)
#define NEGINF -1e30f

#define KW 2048            // storage width of split operands [p1|p2]
#define NCH_P 48           // logical K chunks (64 each) for projections (3x1024)
#define NCH_O 32           // logical K chunks for output gemm (2x1024)

// ======================= scratch (device globals) =======================
__device__ float         g_qv[(size_t)BB * TT * NH];        // q + v  (fp32)
__device__ __nv_bfloat16 g_qu[(size_t)BB * TT * NH];        // bf16(q + u)
__device__ __nv_bfloat16 g_kb[(size_t)BB * SS * NH];        // bf16(k)
__device__ __nv_bfloat16 g_vb[(size_t)BB * SS * NH];        // bf16(val)
__device__ float         g_r [(size_t)SS * NH];             // r (fp32)
__device__ float         g_logits[(size_t)BB * NHEAD * TT * SS];
__device__ float         g_rmax[BB * NHEAD * TT];
__device__ float         g_rsum[BB * NHEAD * TT];
__device__ int           g_qi[BB * TT];
__device__ int           g_ki[BB * SS];

// split operands, stored [p1|p2] (2048 wide); K-folding done by per-chunk offset map
__device__ __nv_bfloat16 g_kvs[(size_t)BB * SS * KW];       // kv splits [4096][2048]
__device__ __nv_bfloat16 g_rs [(size_t)SS * KW];            // rel splits [2048][2048]
__device__ __nv_bfloat16 g_wt [5 * (size_t)NH * KW];        // 5 weights [n][2048]
__device__ __nv_bfloat16 g_attnb[(size_t)BB * TT * NH];     // bf16 attn [2048][1024]

// ======================= PTX helpers =======================
__device__ __forceinline__ uint32_t smem_to_u32(const void* p) {
    uint32_t a;
    asm("{ .reg .u64 t; cvta.to.shared.u64 t, %1; cvt.u32.u64 %0, t; }" : "=r"(a) : "l"(p));
    return a;
}
__device__ __forceinline__ uint32_t swz(uint32_t byte_off) {
    return byte_off ^ ((byte_off >> 3) & 0x70u);
}
#define CP_ASYNC16(dst, src) \
    asm volatile("cp.async.cg.shared.global [%0], [%1], 16;" :: "r"(dst), "l"(src))
#define CP_COMMIT() asm volatile("cp.async.commit_group;" ::: "memory")
#define CP_WAIT(n)  asm volatile("cp.async.wait_group %0;" :: "n"(n) : "memory")
#define LDSM_X4(r0, r1, r2, r3, addr) \
    asm volatile("ldmatrix.sync.aligned.m8n8.x4.shared.b16 {%0,%1,%2,%3}, [%4];" \
        : "=r"(r0), "=r"(r1), "=r"(r2), "=r"(r3) : "r"(addr))
#define MMA16816(d, a0, a1, a2, a3, b0, b1) \
    asm volatile("mma.sync.aligned.m16n8k16.row.col.f32.bf16.bf16.f32 " \
        "{%0,%1,%2,%3}, {%4,%5,%6,%7}, {%8,%9}, {%0,%1,%2,%3};" \
        : "+f"((d)[0]), "+f"((d)[1]), "+f"((d)[2]), "+f"((d)[3]) \
        : "r"(a0), "r"(a1), "r"(a2), "r"(a3), "r"(b0), "r"(b1))

// logical chunk -> source column offset (elements)
// projections: A' = [a1|a1|a2], B' = [b1|b2|b1]; storage [p1|p2]
__device__ __forceinline__ int amap_proj(int c) {
    return (c < 32) ? ((c & 15) << 6) : (1024 + ((c - 32) << 6));
}
__device__ __forceinline__ int bmap_proj(int c) {
    return (c < 16) ? (c << 6) : ((c < 32) ? (1024 + ((c - 16) << 6)) : ((c - 32) << 6));
}
// output gemm: A' = [attn|attn] (storage 1024 wide), B' = [b1|b2]
__device__ __forceinline__ int amap_out(int c) { return (c & 15) << 6; }
__device__ __forceinline__ int bmap_out(int c) {
    return (c < 16) ? (c << 6) : (1024 + ((c - 16) << 6));
}

// ======================= conversion kernels =======================
// fp32 [rows][1024] -> bf16 [rows][2048] = [a1 | a2]
__global__ void split2(const float* __restrict__ src, __nv_bfloat16* __restrict__ dst, int rows)
{
    int i = blockIdx.x * blockDim.x + threadIdx.x;
    if (i >= rows * 1024) return;
    int r = i >> 10, k = i & 1023;
    float a = src[i];
    __nv_bfloat16 h1 = __float2bfloat16(a);
    __nv_bfloat16 h2 = __float2bfloat16(a - __bfloat162float(h1));
    size_t o = (size_t)r * KW + k;
    dst[o] = h1; dst[o + 1024] = h2;
}

// concat(memory, x) -> [a1|a2]  layout [b][s][2048]
__global__ void kv_split(const float* __restrict__ x, const float* __restrict__ mem)
{
    size_t i = (size_t)blockIdx.x * blockDim.x + threadIdx.x;
    if (i >= (size_t)BB * SS * FF) return;
    int b = (int)(i / ((size_t)SS * FF));
    size_t rem = i - (size_t)b * SS * FF;
    int s = (int)(rem / FF);
    int f = (int)(rem - (size_t)s * FF);
    float a = (s < MM) ? mem[((size_t)b * MM + s) * FF + f]
                       : x[((size_t)b * TT + (s - MM)) * FF + f];
    __nv_bfloat16 h1 = __float2bfloat16(a);
    __nv_bfloat16 h2 = __float2bfloat16(a - __bfloat162float(h1));
    size_t o = (size_t)(b * SS + s) * KW + f;
    g_kvs[o] = h1; g_kvs[o + 1024] = h2;
}

// All 5 weights in one launch (z selects). W [1024 k][1024 n] -> Bt [n][2048]
__global__ void transsplit5(const float* __restrict__ W0, const float* __restrict__ W1,
                            const float* __restrict__ W2, const float* __restrict__ W3,
                            const float* __restrict__ W4)
{
    __shared__ float t[32][33];
    const float* Ws[5] = { W0, W1, W2, W3, W4 };
    const float* W = Ws[blockIdx.z];
    __nv_bfloat16* o = g_wt + (size_t)blockIdx.z * NH * KW;
    int k = blockIdx.y * 32 + threadIdx.y;
    int n = blockIdx.x * 32 + threadIdx.x;
    t[threadIdx.y][threadIdx.x] = W[(size_t)k * 1024 + n];
    __syncthreads();
    int nn = blockIdx.x * 32 + threadIdx.y;
    int kk = blockIdx.y * 32 + threadIdx.x;
    float a = t[threadIdx.x][threadIdx.y];
    __nv_bfloat16 h1 = __float2bfloat16(a);
    __nv_bfloat16 h2 = __float2bfloat16(a - __bfloat162float(h1));
    size_t ob = (size_t)nn * KW + kk;
    o[ob] = h1; o[ob + 1024] = h2;
}

// ======================= qi cumsum + ki array =======================
__global__ void calc_qi(const int* __restrict__ ep, const int* __restrict__ dones)
{
    __shared__ int sbuf[TT];
    int b = blockIdx.x, t = threadIdx.x;
    sbuf[t] = dones[b * TT + t];
    __syncthreads();
    for (int off = 1; off < TT; off <<= 1) {
        int add = (t >= off) ? sbuf[t - off] : 0;
        __syncthreads();
        sbuf[t] += add;
        __syncthreads();
    }
    int q = ep[b * MM + (MM - 1)] + sbuf[t];
    g_qi[b * TT + t] = q;
    g_ki[b * SS + MM + t] = q;
    g_ki[b * SS + t] = ep[b * MM + t];
}

// ======================= shared HMMA tile machinery =======================
// 3-stage cp.async pipeline, one __syncthreads per chunk, 2 CTAs/SM.
#define HG_ASTAGE 16384                       // 128 x 64 bf16
#define HG_STAGE  (2 * HG_ASTAGE)             // A + B
#define HG_NSTG   3
#define HG_SMEM   (HG_NSTG * HG_STAGE)        // 96 KB

struct HmmaCore {
    uint32_t sbase;
    int tid, lane, warp, wm, wn, lrow;
    uint32_t col8;
    float acc[4][4][4];

    __device__ __forceinline__ void init(char* smem) {
        sbase = smem_to_u32(smem);
        tid = threadIdx.x; lane = tid & 31; warp = tid >> 5;
        wm = warp >> 2; wn = warp & 3;
        lrow = lane & 15; col8 = (lane >> 4) * 8;
#pragma unroll
        for (int mt = 0; mt < 4; mt++)
#pragma unroll
            for (int nt = 0; nt < 4; nt++)
#pragma unroll
                for (int e = 0; e < 4; e++) acc[mt][nt][e] = 0.f;
    }
    __device__ __forceinline__ void load_stage(int stage, int ka, int kb,
            const __nv_bfloat16* __restrict__ Atile, int ldA,
            const __nv_bfloat16* __restrict__ Btile, int ldB) {
        uint32_t ab = sbase + stage * HG_STAGE;
        uint32_t bb = ab + HG_ASTAGE;
#pragma unroll
        for (int it = 0; it < 8; it++) {
            int idx = tid + it * 256;
            int row = (idx >> 3) & 127, seg = idx & 7;
            uint32_t off = swz((uint32_t)(row * 128 + seg * 16));
            if (idx < 1024) CP_ASYNC16(ab + off, Atile + (size_t)row * ldA + ka + seg * 8);
            else            CP_ASYNC16(bb + off, Btile + (size_t)row * ldB + kb + seg * 8);
        }
    }
    __device__ __forceinline__ void compute(int stage) {
        uint32_t ab = sbase + stage * HG_STAGE;
        uint32_t bb = ab + HG_ASTAGE;
#pragma unroll
        for (int kk = 0; kk < 4; kk++) {
            uint32_t af[4][4], bfr[2][4];
#pragma unroll
            for (int mt = 0; mt < 4; mt++) {
                uint32_t addr = ab + swz((uint32_t)((wm * 64 + mt * 16 + lrow) * 128 +
                                                    (kk * 16 + col8) * 2));
                LDSM_X4(af[mt][0], af[mt][1], af[mt][2], af[mt][3], addr);
            }
#pragma unroll
            for (int bt = 0; bt < 2; bt++) {
                uint32_t addr = bb + swz((uint32_t)((wn * 32 + bt * 16 + lrow) * 128 +
                                                    (kk * 16 + col8) * 2));
                LDSM_X4(bfr[bt][0], bfr[bt][1], bfr[bt][2], bfr[bt][3], addr);
            }
#pragma unroll
            for (int mt = 0; mt < 4; mt++)
#pragma unroll
                for (int bt = 0; bt < 2; bt++) {
                    MMA16816(acc[mt][2 * bt],     af[mt][0], af[mt][1], af[mt][2], af[mt][3],
                             bfr[bt][0], bfr[bt][2]);
                    MMA16816(acc[mt][2 * bt + 1], af[mt][0], af[mt][1], af[mt][2], af[mt][3],
                             bfr[bt][1], bfr[bt][3]);
                }
        }
    }
    // MODE 0: projection K map (48 chunks), MODE 1: output K map (32 chunks)
    template <int MODE>
    __device__ __forceinline__ void run(const __nv_bfloat16* Atile, int ldA,
                                        const __nv_bfloat16* Btile, int ldB) {
        const int n = (MODE == 0) ? NCH_P : NCH_O;
        auto am = [](int c) { return (MODE == 0) ? amap_proj(c) : amap_out(c); };
        auto bm = [](int c) { return (MODE == 0) ? bmap_proj(c) : bmap_out(c); };
        load_stage(0, am(0), bm(0), Atile, ldA, Btile, ldB);
        CP_COMMIT();
        load_stage(1, am(1), bm(1), Atile, ldA, Btile, ldB);
        CP_COMMIT();
        int st = 0;
        for (int c = 0; c < n; c++) {
            CP_WAIT(1);
            __syncthreads();
            compute(st);
            int nc = c + 2;
            int ns = st + 2; if (ns >= HG_NSTG) ns -= HG_NSTG;
            if (nc < n) load_stage(ns, am(nc), bm(nc), Atile, ldA, Btile, ldB);
            CP_COMMIT();               // empty group in tail keeps wait counts aligned
            st = (st + 1 == HG_NSTG) ? 0 : st + 1;
        }
    }
};

// ======================= merged projection GEMM (q, k, v, r) =======================
// grid = (8, 96): y 0..15 -> q | 16..47 -> k | 48..79 -> v | 80..95 -> r
__global__ void __launch_bounds__(256, 2) proj_gemm(
    const float* __restrict__ bias_v, const float* __restrict__ bias_u)
{
    extern __shared__ char smem[];
    const int gy = blockIdx.y;
    const int c0 = blockIdx.x * 128;
    const size_t WS = (size_t)NH * KW;

    int gid, rt;
    if      (gy < 16) { gid = 0; rt = gy; }
    else if (gy < 48) { gid = 1; rt = gy - 16; }
    else if (gy < 80) { gid = 2; rt = gy - 48; }
    else              { gid = 3; rt = gy - 80; }
    const int r0 = rt * 128;

    const __nv_bfloat16* Atile;
    if (gid == 0) {                 // q rows are the x rows inside g_kvs
        int b = r0 >> 10;
        Atile = g_kvs + (size_t)(b * SS + MM + (r0 & 1023)) * KW;
    } else if (gid == 3) {
        Atile = g_rs + (size_t)r0 * KW;
    } else {
        Atile = g_kvs + (size_t)r0 * KW;
    }
    const __nv_bfloat16* Btile = g_wt + (size_t)gid * WS + (size_t)c0 * KW;

    HmmaCore h;
    h.init(smem);
    h.run<0>(Atile, KW, Btile, KW);

#pragma unroll
    for (int mt = 0; mt < 4; mt++) {
        int rbase = r0 + h.wm * 64 + mt * 16 + (h.lane >> 2);
#pragma unroll
        for (int nt = 0; nt < 4; nt++) {
            int cbase = c0 + h.wn * 32 + nt * 8 + (h.lane & 3) * 2;
#pragma unroll
            for (int e = 0; e < 4; e++) {
                int r = rbase + (e >> 1) * 8;
                int c = cbase + (e & 1);
                float vv = h.acc[mt][nt][e];
                size_t o = (size_t)r * 1024 + c;
                if (gid == 0) {
                    g_qv[o] = vv + bias_v[c];
                    g_qu[o] = __float2bfloat16(vv + bias_u[c]);
                } else if (gid == 1) {
                    g_kb[o] = __float2bfloat16(vv);
                } else if (gid == 2) {
                    g_vb[o] = __float2bfloat16(vv);
                } else {
                    g_r[o] = vv;
                }
            }
        }
    }
}

// ======================= output GEMM: [attn|attn] @ [b1|b2] + b_out =======================
__global__ void __launch_bounds__(256, 2) out_gemm(const float* __restrict__ bo,
                                                   float* __restrict__ out)
{
    extern __shared__ char smem[];
    const int r0 = blockIdx.y * 128, c0 = blockIdx.x * 128;
    const __nv_bfloat16* Atile = g_attnb + (size_t)r0 * NH;
    const __nv_bfloat16* Btile = g_wt + 4 * (size_t)NH * KW + (size_t)c0 * KW;

    HmmaCore h;
    h.init(smem);
    h.run<1>(Atile, NH, Btile, KW);

#pragma unroll
    for (int mt = 0; mt < 4; mt++) {
        int rbase = r0 + h.wm * 64 + mt * 16 + (h.lane >> 2);
#pragma unroll
        for (int nt = 0; nt < 4; nt++) {
            int cbase = c0 + h.wn * 32 + nt * 8 + (h.lane & 3) * 2;
#pragma unroll
            for (int e = 0; e < 4; e++) {
                int r = rbase + (e >> 1) * 8;
                int c = cbase + (e & 1);
                out[(size_t)r * 1024 + c] = h.acc[mt][nt][e] + bo[c];
            }
        }
    }
}

// ======================= ATT1: masked logits + online row max/sum =======================
__global__ void __launch_bounds__(256) att_logits(const int* __restrict__ ep_idx)
{
    extern __shared__ float sm[];
    float* qu_s = sm;
    float* qv_s = qu_s + 64 * 65;
    float* k_s  = qv_s + 64 * 65;
    float* r_s  = k_s  + 64 * 65;
    int* qi_s = (int*)(r_s + 128 * 65);
    int* ki_s = qi_s + 64;

    const int tid = threadIdx.x;
    const int bn = blockIdx.x;
    const int b = bn >> 4, n = bn & 15;
    const int t0 = blockIdx.y * 64;
    const int ty = tid >> 4, tx = tid & 15;
    const int qbase = ty * 4, sbase = tx * 4;

    for (int e = tid; e < 4096; e += 256) {
        int q = e >> 6, h = e & 63;
        size_t row = (size_t)(b * TT + t0 + q) * NH + n * 64 + h;
        qu_s[q * 65 + h] = __bfloat162float(g_qu[row]);
        qv_s[q * 65 + h] = g_qv[row];
    }
    if (tid < 64) qi_s[tid] = g_qi[b * TT + t0 + tid];
    __syncthreads();

    const int qlo = qi_s[0], qhi = qi_s[63];
    const int causal_max = MM + t0 + 63;

    float rmax[4], rsum[4];
#pragma unroll
    for (int i = 0; i < 4; i++) { rmax[i] = -INFINITY; rsum[i] = 0.f; }

    for (int s0 = 0; s0 < SS; s0 += 64) {
        if (s0 > causal_max) break;
        {
            int klo = g_ki[b * SS + s0];
            int khi = g_ki[b * SS + s0 + 63];
            if (khi < qlo || klo > qhi) continue;
        }
        __syncthreads();
        for (int e = tid; e < 4096; e += 256) {
            int s = e >> 6, h = e & 63;
            k_s[s * 65 + h] = __bfloat162float(g_kb[(size_t)(b * SS + s0 + s) * NH + n * 64 + h]);
        }
        const int base = s0 - t0 + (TT - 64);
        for (int e = tid; e < 8192; e += 256) {
            int j = e >> 6, h = e & 63;
            int m = base + j; m = (m > SS - 1) ? SS - 1 : m; m = (m < 0) ? 0 : m;
            r_s[j * 65 + h] = g_r[(size_t)m * NH + n * 64 + h];
        }
        if (tid < 64) {
            int s = s0 + tid;
            ki_s[tid] = (s < MM) ? ep_idx[b * MM + s] : g_qi[b * TT + (s - MM)];
        }
        __syncthreads();

        float qk[4][4], bbx[4][4];
#pragma unroll
        for (int i = 0; i < 4; i++)
#pragma unroll
            for (int j = 0; j < 4; j++) { qk[i][j] = 0.f; bbx[i][j] = 0.f; }
        const int rrow0 = sbase - qbase + 60;
#pragma unroll 4
        for (int h = 0; h < 64; h++) {
            float au[4], av[4], kk4[4], rr[7];
#pragma unroll
            for (int i = 0; i < 4; i++) {
                au[i] = qu_s[(qbase + i) * 65 + h];
                av[i] = qv_s[(qbase + i) * 65 + h];
            }
#pragma unroll
            for (int j = 0; j < 4; j++) kk4[j] = k_s[(sbase + j) * 65 + h];
#pragma unroll
            for (int d = 0; d < 7; d++) rr[d] = r_s[(rrow0 + d) * 65 + h];
#pragma unroll
            for (int i = 0; i < 4; i++)
#pragma unroll
                for (int j = 0; j < 4; j++) {
                    qk[i][j]  = fmaf(au[i], kk4[j], qk[i][j]);
                    bbx[i][j] = fmaf(av[i], rr[j - i + 3], bbx[i][j]);
                }
        }
        float lv[4][4];
#pragma unroll
        for (int i = 0; i < 4; i++) {
            int tg = t0 + qbase + i;
#pragma unroll
            for (int j = 0; j < 4; j++) {
                int sg = s0 + sbase + j;
                float l = __bfloat162float(__float2bfloat16(qk[i][j])) * SCALE + bbx[i][j] * SCALE;
                bool ok = (sg <= MM + tg) && (qi_s[qbase + i] == ki_s[sbase + j]);
                l = ok ? l : NEGINF;
                lv[i][j] = l;
                g_logits[((size_t)bn * TT + tg) * SS + sg] = l;
            }
        }
#pragma unroll
        for (int i = 0; i < 4; i++) {
            float tm = fmaxf(fmaxf(lv[i][0], lv[i][1]), fmaxf(lv[i][2], lv[i][3]));
#pragma unroll
            for (int msk = 1; msk < 16; msk <<= 1)
                tm = fmaxf(tm, __shfl_xor_sync(0xffffffffu, tm, msk));
            float nm = fmaxf(rmax[i], tm);
            float ps = expf(lv[i][0] - nm) + expf(lv[i][1] - nm) +
                       expf(lv[i][2] - nm) + expf(lv[i][3] - nm);
#pragma unroll
            for (int msk = 1; msk < 16; msk <<= 1)
                ps += __shfl_xor_sync(0xffffffffu, ps, msk);
            rsum[i] = rsum[i] * expf(rmax[i] - nm) + ps;
            rmax[i] = nm;
        }
    }
    if (tx == 0) {
#pragma unroll
        for (int i = 0; i < 4; i++) {
            int tg = t0 + qbase + i;
            g_rmax[bn * TT + tg] = rmax[i];
            g_rsum[bn * TT + tg] = rsum[i];
        }
    }
}

// ======================= ATT2: probs (bf16 after normalization) @ val =======================
__global__ void __launch_bounds__(256) att_pv()
{
    __shared__ float p_s[64][65];
    __shared__ float v_s[64][65];
    __shared__ float rm_s[64], rs_s[64];
    const int tid = threadIdx.x;
    const int bn = blockIdx.x;
    const int b = bn >> 4, n = bn & 15;
    const int t0 = blockIdx.y * 64;
    const int ty = tid >> 4, tx = tid & 15;

    if (tid < 64) {
        rm_s[tid] = g_rmax[bn * TT + t0 + tid];
        rs_s[tid] = g_rsum[bn * TT + t0 + tid];
    }
    const int qlo = g_qi[b * TT + t0];
    const int qhi = g_qi[b * TT + t0 + 63];
    const int causal_max = MM + t0 + 63;

    float acc[4][4];
#pragma unroll
    for (int i = 0; i < 4; i++)
#pragma unroll
        for (int j = 0; j < 4; j++) acc[i][j] = 0.f;

    for (int s0 = 0; s0 < SS; s0 += 64) {
        if (s0 > causal_max) break;
        {
            int klo = g_ki[b * SS + s0];
            int khi = g_ki[b * SS + s0 + 63];
            if (khi < qlo || klo > qhi) continue;
        }
        __syncthreads();
        for (int e = tid; e < 4096; e += 256) {
            int q = e >> 6, s = e & 63;
            float L = g_logits[((size_t)bn * TT + t0 + q) * SS + s0 + s];
            float p = expf(L - rm_s[q]) / rs_s[q];
            p_s[q][s] = __bfloat162float(__float2bfloat16(p));
        }
        for (int e = tid; e < 4096; e += 256) {
            int s = e >> 6, h = e & 63;
            v_s[s][h] = __bfloat162float(g_vb[(size_t)(b * SS + s0 + s) * NH + n * 64 + h]);
        }
        __syncthreads();
#pragma unroll 8
        for (int s = 0; s < 64; s++) {
            float pv[4], vv[4];
#pragma unroll
            for (int i = 0; i < 4; i++) pv[i] = p_s[ty * 4 + i][s];
#pragma unroll
            for (int j = 0; j < 4; j++) vv[j] = v_s[s][tx * 4 + j];
#pragma unroll
            for (int i = 0; i < 4; i++)
#pragma unroll
                for (int j = 0; j < 4; j++)
                    acc[i][j] = fmaf(pv[i], vv[j], acc[i][j]);
        }
    }
#pragma unroll
    for (int i = 0; i < 4; i++) {
        int t = t0 + ty * 4 + i;
#pragma unroll
        for (int j = 0; j < 4; j++) {
            g_attnb[(size_t)(b * TT + t) * NH + n * 64 + tx * 4 + j] =
                __float2bfloat16(acc[i][j]);
        }
    }
}

// ======================= launch =======================
extern "C" void kernel_launch(void* const* d_in, const int* in_sizes, int n_in,
                              void* d_out, int out_size)
{
    const float* x    = (const float*)d_in[0];
    const float* rel  = (const float*)d_in[1];
    const float* mem  = (const float*)d_in[2];
    const int*   ep   = (const int*)d_in[3];
    const int*   dones= (const int*)d_in[4];
    const float* Wq   = (const float*)d_in[5];
    const float* Wk   = (const float*)d_in[6];
    const float* Wv   = (const float*)d_in[7];
    const float* Wr   = (const float*)d_in[8];
    const float* u    = (const float*)d_in[9];
    const float* v    = (const float*)d_in[10];
    const float* Wout = (const float*)d_in[11];
    const float* bo   = (const float*)d_in[12];
    float* out = (float*)d_out;
    (void)in_sizes; (void)n_in; (void)out_size;

    void* prs;
    cudaGetSymbolAddress(&prs, g_rs);
    __nv_bfloat16* rs = (__nv_bfloat16*)prs;

    // ---- conversions ----
    kv_split<<<(int)(((size_t)BB * SS * FF + 255) / 256), 256>>>(x, mem);
    split2<<<(SS * FF + 255) / 256, 256>>>(rel, rs, SS);
    transsplit5<<<dim3(32, 32, 5), dim3(32, 32)>>>(Wq, Wk, Wv, Wr, Wout);
    calc_qi<<<BB, TT>>>(ep, dones);

    // ---- merged projection GEMMs (q, k, v, r) ----
    cudaFuncSetAttribute(proj_gemm, cudaFuncAttributeMaxDynamicSharedMemorySize, HG_SMEM);
    proj_gemm<<<dim3(8, 96), 256, HG_SMEM>>>(v, u);

    // ---- attention (tile-skipped) ----
    const int att1_smem = (3 * 64 * 65 + 128 * 65) * (int)sizeof(float) + 128 * (int)sizeof(int);
    cudaFuncSetAttribute(att_logits, cudaFuncAttributeMaxDynamicSharedMemorySize, att1_smem);
    att_logits<<<dim3(BB * NHEAD, TT / 64), 256, att1_smem>>>(ep);
    att_pv<<<dim3(BB * NHEAD, TT / 64), 256>>>();

    // ---- output projection ----
    cudaFuncSetAttribute(out_gemm, cudaFuncAttributeMaxDynamicSharedMemorySize, HG_SMEM);
    out_gemm<<<dim3(8, 16), 256, HG_SMEM>>>(bo, out);
}

// round 8
// speedup vs baseline: 5.4187x; 1.0842x over previous
#include <cuda_runtime.h>
#include <cuda_bf16.h>
#include <cstdint>
#include <math.h>

#define BB 2
#define TT 1024
#define MM 1024
#define FF 1024
#define NHEAD 16
#define HH 64
#define SS 2048            // M + T
#define NH 1024            // N * H
#define SCALE 0.125f       // 1/sqrt(64)
#define NEGINF -1e30f

#define KW 2048            // storage width of split operands [p1|p2]
#define NCH_P 48           // logical K chunks (64 each) for projections (3x1024)
#define NCH_O 32           // logical K chunks for output gemm (2x1024)

// ======================= scratch (device globals) =======================
__device__ float         g_qv[(size_t)BB * TT * NH];
__device__ __nv_bfloat16 g_qu[(size_t)BB * TT * NH];
__device__ __nv_bfloat16 g_kb[(size_t)BB * SS * NH];
__device__ __nv_bfloat16 g_vb[(size_t)BB * SS * NH];
__device__ float         g_r [(size_t)SS * NH];
__device__ float         g_logits[(size_t)BB * NHEAD * TT * SS];
__device__ int           g_qi[BB * TT];
__device__ int           g_ki[BB * SS];

__device__ __nv_bfloat16 g_kvs[(size_t)BB * SS * KW];       // kv splits [4096][2048]
__device__ __nv_bfloat16 g_rs [(size_t)SS * KW];            // rel splits [2048][2048]
__device__ __nv_bfloat16 g_wt [5 * (size_t)NH * KW];        // 5 weights [n][2048]
__device__ __nv_bfloat16 g_attnb[(size_t)BB * TT * NH];     // bf16 attn

// ======================= PTX helpers =======================
__device__ __forceinline__ uint32_t smem_to_u32(const void* p) {
    uint32_t a;
    asm("{ .reg .u64 t; cvta.to.shared.u64 t, %1; cvt.u32.u64 %0, t; }" : "=r"(a) : "l"(p));
    return a;
}
__device__ __forceinline__ uint32_t swz(uint32_t byte_off) {
    return byte_off ^ ((byte_off >> 3) & 0x70u);
}
#define CP_ASYNC16(dst, src) \
    asm volatile("cp.async.cg.shared.global [%0], [%1], 16;" :: "r"(dst), "l"(src))
#define CP_COMMIT() asm volatile("cp.async.commit_group;" ::: "memory")
#define CP_WAIT(n)  asm volatile("cp.async.wait_group %0;" :: "n"(n) : "memory")
#define LDSM_X4(r0, r1, r2, r3, addr) \
    asm volatile("ldmatrix.sync.aligned.m8n8.x4.shared.b16 {%0,%1,%2,%3}, [%4];" \
        : "=r"(r0), "=r"(r1), "=r"(r2), "=r"(r3) : "r"(addr))
#define MMA16816(d, a0, a1, a2, a3, b0, b1) \
    asm volatile("mma.sync.aligned.m16n8k16.row.col.f32.bf16.bf16.f32 " \
        "{%0,%1,%2,%3}, {%4,%5,%6,%7}, {%8,%9}, {%0,%1,%2,%3};" \
        : "+f"((d)[0]), "+f"((d)[1]), "+f"((d)[2]), "+f"((d)[3]) \
        : "r"(a0), "r"(a1), "r"(a2), "r"(a3), "r"(b0), "r"(b1))

// logical chunk -> source column offset (elements)
__device__ __forceinline__ int amap_proj(int c) {
    return (c < 32) ? ((c & 15) << 6) : (1024 + ((c - 32) << 6));
}
__device__ __forceinline__ int bmap_proj(int c) {
    return (c < 16) ? (c << 6) : ((c < 32) ? (1024 + ((c - 16) << 6)) : ((c - 32) << 6));
}
__device__ __forceinline__ int amap_out(int c) { return (c & 15) << 6; }
__device__ __forceinline__ int bmap_out(int c) {
    return (c < 16) ? (c << 6) : (1024 + ((c - 16) << 6));
}

// ======================= prep mega-kernel =======================
// block ranges: [0,4096) kv_split rows | [4096,6144) rel rows | [6144,11264) W tiles | [11264,11266) qi scan
#define PREP_A 4096
#define PREP_B 2048
#define PREP_C 5120
#define PREP_GRID (PREP_A + PREP_B + PREP_C + 2)

__global__ void __launch_bounds__(256) prep(
    const float* __restrict__ x, const float* __restrict__ mem, const float* __restrict__ rel,
    const float* __restrict__ W0, const float* __restrict__ W1, const float* __restrict__ W2,
    const float* __restrict__ W3, const float* __restrict__ W4,
    const int* __restrict__ ep, const int* __restrict__ dones)
{
    __shared__ float tsm[32][33];
    __shared__ int   sb[256];
    const int g = blockIdx.x;
    const int tid = threadIdx.x;

    if (g < PREP_A) {
        // kv_split: one (b,s) row per block, 4 elements per thread
        int b = g >> 11, s = g & 2047;
        int f = tid * 4;
        const float* src = (s < MM) ? (mem + ((size_t)(b * MM + s)) * FF + f)
                                    : (x + ((size_t)(b * TT + (s - MM))) * FF + f);
        float4 a = *(const float4*)src;
        __nv_bfloat16 h1[4], h2[4];
        float av[4] = { a.x, a.y, a.z, a.w };
#pragma unroll
        for (int j = 0; j < 4; j++) {
            h1[j] = __float2bfloat16(av[j]);
            h2[j] = __float2bfloat16(av[j] - __bfloat162float(h1[j]));
        }
        size_t o = (size_t)g * KW + f;
        *(uint2*)&g_kvs[o] = *(uint2*)h1;
        *(uint2*)&g_kvs[o + 1024] = *(uint2*)h2;
    } else if (g < PREP_A + PREP_B) {
        // rel split: one row per block
        int r = g - PREP_A;
        int f = tid * 4;
        float4 a = *(const float4*)(rel + (size_t)r * FF + f);
        __nv_bfloat16 h1[4], h2[4];
        float av[4] = { a.x, a.y, a.z, a.w };
#pragma unroll
        for (int j = 0; j < 4; j++) {
            h1[j] = __float2bfloat16(av[j]);
            h2[j] = __float2bfloat16(av[j] - __bfloat162float(h1[j]));
        }
        size_t o = (size_t)r * KW + f;
        *(uint2*)&g_rs[o] = *(uint2*)h1;
        *(uint2*)&g_rs[o + 1024] = *(uint2*)h2;
    } else if (g < PREP_A + PREP_B + PREP_C) {
        // weight transpose+split: one 32x32 tile
        int tt = g - (PREP_A + PREP_B);
        int w = tt >> 10, tile = tt & 1023;
        int bx = tile & 31, by = tile >> 5;          // bx: n block, by: k block
        const float* Ws[5] = { W0, W1, W2, W3, W4 };
        const float* W = Ws[w];
        __nv_bfloat16* o = g_wt + (size_t)w * NH * KW;
#pragma unroll
        for (int i = 0; i < 4; i++) {
            int idx = tid + i * 256;
            int ky = idx >> 5, nx = idx & 31;
            tsm[ky][nx] = W[(size_t)(by * 32 + ky) * 1024 + bx * 32 + nx];
        }
        __syncthreads();
#pragma unroll
        for (int i = 0; i < 4; i++) {
            int idx = tid + i * 256;
            int nl = idx >> 5, kl = idx & 31;
            float a = tsm[kl][nl];
            __nv_bfloat16 h1 = __float2bfloat16(a);
            __nv_bfloat16 h2 = __float2bfloat16(a - __bfloat162float(h1));
            size_t ob = (size_t)(bx * 32 + nl) * KW + by * 32 + kl;
            o[ob] = h1; o[ob + 1024] = h2;
        }
    } else {
        // calc_qi: 256-thread scan over 1024 dones
        int b = g - (PREP_A + PREP_B + PREP_C);
        int t4 = tid * 4;
        int d0 = dones[b * TT + t4], d1 = dones[b * TT + t4 + 1];
        int d2 = dones[b * TT + t4 + 2], d3 = dones[b * TT + t4 + 3];
        int l0 = d0, l1 = l0 + d1, l2 = l1 + d2, l3 = l2 + d3;
        sb[tid] = l3;
        __syncthreads();
        for (int off = 1; off < 256; off <<= 1) {
            int add = (tid >= off) ? sb[tid - off] : 0;
            __syncthreads();
            sb[tid] += add;
            __syncthreads();
        }
        int excl = sb[tid] - l3;
        int base = ep[b * MM + (MM - 1)];
        int q[4] = { base + excl + l0, base + excl + l1, base + excl + l2, base + excl + l3 };
#pragma unroll
        for (int j = 0; j < 4; j++) {
            g_qi[b * TT + t4 + j] = q[j];
            g_ki[b * SS + MM + t4 + j] = q[j];
            g_ki[b * SS + t4 + j] = ep[b * MM + t4 + j];
        }
    }
}

// ======================= shared HMMA tile machinery =======================
#define HG_ASTAGE 16384
#define HG_STAGE  (2 * HG_ASTAGE)
#define HG_NSTG   3
#define HG_SMEM   (HG_NSTG * HG_STAGE)        // 96 KB

struct HmmaCore {
    uint32_t sbase;
    int tid, lane, warp, wm, wn, lrow;
    uint32_t col8;
    float acc[4][4][4];

    __device__ __forceinline__ void init(char* smem) {
        sbase = smem_to_u32(smem);
        tid = threadIdx.x; lane = tid & 31; warp = tid >> 5;
        wm = warp >> 2; wn = warp & 3;
        lrow = lane & 15; col8 = (lane >> 4) * 8;
#pragma unroll
        for (int mt = 0; mt < 4; mt++)
#pragma unroll
            for (int nt = 0; nt < 4; nt++)
#pragma unroll
                for (int e = 0; e < 4; e++) acc[mt][nt][e] = 0.f;
    }
    __device__ __forceinline__ void load_stage(int stage, int ka, int kb,
            const __nv_bfloat16* __restrict__ Atile, int ldA,
            const __nv_bfloat16* __restrict__ Btile, int ldB) {
        uint32_t ab = sbase + stage * HG_STAGE;
        uint32_t bb = ab + HG_ASTAGE;
#pragma unroll
        for (int it = 0; it < 8; it++) {
            int idx = tid + it * 256;
            int row = (idx >> 3) & 127, seg = idx & 7;
            uint32_t off = swz((uint32_t)(row * 128 + seg * 16));
            if (idx < 1024) CP_ASYNC16(ab + off, Atile + (size_t)row * ldA + ka + seg * 8);
            else            CP_ASYNC16(bb + off, Btile + (size_t)row * ldB + kb + seg * 8);
        }
    }
    __device__ __forceinline__ void compute(int stage) {
        uint32_t ab = sbase + stage * HG_STAGE;
        uint32_t bb = ab + HG_ASTAGE;
#pragma unroll
        for (int kk = 0; kk < 4; kk++) {
            uint32_t bfr[2][4];
#pragma unroll
            for (int bt = 0; bt < 2; bt++) {
                uint32_t addr = bb + swz((uint32_t)((wn * 32 + bt * 16 + lrow) * 128 +
                                                    (kk * 16 + col8) * 2));
                LDSM_X4(bfr[bt][0], bfr[bt][1], bfr[bt][2], bfr[bt][3], addr);
            }
#pragma unroll
            for (int mt = 0; mt < 4; mt++) {
                uint32_t a0, a1, a2, a3;
                uint32_t addr = ab + swz((uint32_t)((wm * 64 + mt * 16 + lrow) * 128 +
                                                    (kk * 16 + col8) * 2));
                LDSM_X4(a0, a1, a2, a3, addr);
#pragma unroll
                for (int bt = 0; bt < 2; bt++) {
                    MMA16816(acc[mt][2 * bt],     a0, a1, a2, a3, bfr[bt][0], bfr[bt][2]);
                    MMA16816(acc[mt][2 * bt + 1], a0, a1, a2, a3, bfr[bt][1], bfr[bt][3]);
                }
            }
        }
    }
    template <int MODE>
    __device__ __forceinline__ void run(const __nv_bfloat16* Atile, int ldA,
                                        const __nv_bfloat16* Btile, int ldB) {
        const int n = (MODE == 0) ? NCH_P : NCH_O;
        auto am = [](int c) { return (MODE == 0) ? amap_proj(c) : amap_out(c); };
        auto bm = [](int c) { return (MODE == 0) ? bmap_proj(c) : bmap_out(c); };
        load_stage(0, am(0), bm(0), Atile, ldA, Btile, ldB);
        CP_COMMIT();
        load_stage(1, am(1), bm(1), Atile, ldA, Btile, ldB);
        CP_COMMIT();
        int st = 0;
        for (int c = 0; c < n; c++) {
            CP_WAIT(1);
            __syncthreads();
            compute(st);
            int nc = c + 2;
            int ns = st + 2; if (ns >= HG_NSTG) ns -= HG_NSTG;
            if (nc < n) load_stage(ns, am(nc), bm(nc), Atile, ldA, Btile, ldB);
            CP_COMMIT();
            st = (st + 1 == HG_NSTG) ? 0 : st + 1;
        }
    }
};

// ======================= merged projection GEMM (q, k, v, r) =======================
__global__ void __launch_bounds__(256, 2) proj_gemm(
    const float* __restrict__ bias_v, const float* __restrict__ bias_u)
{
    extern __shared__ char smem[];
    const int gy = blockIdx.y;
    const int c0 = blockIdx.x * 128;
    const size_t WS = (size_t)NH * KW;

    int gid, rt;
    if      (gy < 16) { gid = 0; rt = gy; }
    else if (gy < 48) { gid = 1; rt = gy - 16; }
    else if (gy < 80) { gid = 2; rt = gy - 48; }
    else              { gid = 3; rt = gy - 80; }
    const int r0 = rt * 128;

    const __nv_bfloat16* Atile;
    if (gid == 0) {
        int b = r0 >> 10;
        Atile = g_kvs + (size_t)(b * SS + MM + (r0 & 1023)) * KW;
    } else if (gid == 3) {
        Atile = g_rs + (size_t)r0 * KW;
    } else {
        Atile = g_kvs + (size_t)r0 * KW;
    }
    const __nv_bfloat16* Btile = g_wt + (size_t)gid * WS + (size_t)c0 * KW;

    HmmaCore h;
    h.init(smem);
    h.run<0>(Atile, KW, Btile, KW);

#pragma unroll
    for (int mt = 0; mt < 4; mt++) {
        int rbase = r0 + h.wm * 64 + mt * 16 + (h.lane >> 2);
#pragma unroll
        for (int nt = 0; nt < 4; nt++) {
            int cbase = c0 + h.wn * 32 + nt * 8 + (h.lane & 3) * 2;
#pragma unroll
            for (int e = 0; e < 4; e++) {
                int r = rbase + (e >> 1) * 8;
                int c = cbase + (e & 1);
                float vv = h.acc[mt][nt][e];
                size_t o = (size_t)r * 1024 + c;
                if (gid == 0) {
                    g_qv[o] = vv + bias_v[c];
                    g_qu[o] = __float2bfloat16(vv + bias_u[c]);
                } else if (gid == 1) {
                    g_kb[o] = __float2bfloat16(vv);
                } else if (gid == 2) {
                    g_vb[o] = __float2bfloat16(vv);
                } else {
                    g_r[o] = vv;
                }
            }
        }
    }
}

// ======================= output GEMM =======================
__global__ void __launch_bounds__(256, 2) out_gemm(const float* __restrict__ bo,
                                                   float* __restrict__ out)
{
    extern __shared__ char smem[];
    const int r0 = blockIdx.y * 128, c0 = blockIdx.x * 128;
    const __nv_bfloat16* Atile = g_attnb + (size_t)r0 * NH;
    const __nv_bfloat16* Btile = g_wt + 4 * (size_t)NH * KW + (size_t)c0 * KW;

    HmmaCore h;
    h.init(smem);
    h.run<1>(Atile, NH, Btile, KW);

#pragma unroll
    for (int mt = 0; mt < 4; mt++) {
        int rbase = r0 + h.wm * 64 + mt * 16 + (h.lane >> 2);
#pragma unroll
        for (int nt = 0; nt < 4; nt++) {
            int cbase = c0 + h.wn * 32 + nt * 8 + (h.lane & 3) * 2;
#pragma unroll
            for (int e = 0; e < 4; e++) {
                int r = rbase + (e >> 1) * 8;
                int c = cbase + (e & 1);
                out[(size_t)r * 1024 + c] = h.acc[mt][nt][e] + bo[c];
            }
        }
    }
}

// ======================= fused attention =======================
__global__ void __launch_bounds__(256) att_fused(const int* __restrict__ ep_idx)
{
    extern __shared__ float sm[];
    float* qu_s = sm;                  // 64*65 (phase2: p_s)
    float* qv_s = qu_s + 64 * 65;      // 64*65 (phase2: v_s)
    float* k_s  = qv_s + 64 * 65;      // 64*65
    float* r_s  = k_s  + 64 * 65;      // 128*65
    float* rm_s = r_s + 128 * 65;      // 64
    float* rs_s = rm_s + 64;           // 64
    int* qi_s = (int*)(rs_s + 64);     // 64
    int* ki_s = qi_s + 64;             // 64

    const int tid = threadIdx.x;
    const int bn = blockIdx.x;
    const int b = bn >> 4, n = bn & 15;
    const int t0 = blockIdx.y * 64;
    const int ty = tid >> 4, tx = tid & 15;
    const int qbase = ty * 4, sbase = tx * 4;

    // ---------- phase 1: logits + online max/sum ----------
    for (int e = tid; e < 4096; e += 256) {
        int q = e >> 6, h = e & 63;
        size_t row = (size_t)(b * TT + t0 + q) * NH + n * 64 + h;
        qu_s[q * 65 + h] = __bfloat162float(g_qu[row]);
        qv_s[q * 65 + h] = g_qv[row];
    }
    if (tid < 64) qi_s[tid] = g_qi[b * TT + t0 + tid];
    __syncthreads();

    const int qlo = qi_s[0], qhi = qi_s[63];
    const int causal_max = MM + t0 + 63;

    float rmax[4], rsum[4];
#pragma unroll
    for (int i = 0; i < 4; i++) { rmax[i] = -INFINITY; rsum[i] = 0.f; }

    for (int s0 = 0; s0 < SS; s0 += 64) {
        if (s0 > causal_max) break;
        {
            int klo = g_ki[b * SS + s0];
            int khi = g_ki[b * SS + s0 + 63];
            if (khi < qlo || klo > qhi) continue;
        }
        __syncthreads();
        for (int e = tid; e < 4096; e += 256) {
            int s = e >> 6, h = e & 63;
            k_s[s * 65 + h] = __bfloat162float(g_kb[(size_t)(b * SS + s0 + s) * NH + n * 64 + h]);
        }
        const int base = s0 - t0 + (TT - 64);
        for (int e = tid; e < 8192; e += 256) {
            int j = e >> 6, h = e & 63;
            int m = base + j; m = (m > SS - 1) ? SS - 1 : m; m = (m < 0) ? 0 : m;
            r_s[j * 65 + h] = g_r[(size_t)m * NH + n * 64 + h];
        }
        if (tid < 64) {
            int s = s0 + tid;
            ki_s[tid] = (s < MM) ? ep_idx[b * MM + s] : g_qi[b * TT + (s - MM)];
        }
        __syncthreads();

        float qk[4][4], bbx[4][4];
#pragma unroll
        for (int i = 0; i < 4; i++)
#pragma unroll
            for (int j = 0; j < 4; j++) { qk[i][j] = 0.f; bbx[i][j] = 0.f; }
        const int rrow0 = sbase - qbase + 60;
#pragma unroll 4
        for (int h = 0; h < 64; h++) {
            float au[4], av[4], kk4[4], rr[7];
#pragma unroll
            for (int i = 0; i < 4; i++) {
                au[i] = qu_s[(qbase + i) * 65 + h];
                av[i] = qv_s[(qbase + i) * 65 + h];
            }
#pragma unroll
            for (int j = 0; j < 4; j++) kk4[j] = k_s[(sbase + j) * 65 + h];
#pragma unroll
            for (int d = 0; d < 7; d++) rr[d] = r_s[(rrow0 + d) * 65 + h];
#pragma unroll
            for (int i = 0; i < 4; i++)
#pragma unroll
                for (int j = 0; j < 4; j++) {
                    qk[i][j]  = fmaf(au[i], kk4[j], qk[i][j]);
                    bbx[i][j] = fmaf(av[i], rr[j - i + 3], bbx[i][j]);
                }
        }
        float lv[4][4];
#pragma unroll
        for (int i = 0; i < 4; i++) {
            int tg = t0 + qbase + i;
#pragma unroll
            for (int j = 0; j < 4; j++) {
                int sg = s0 + sbase + j;
                float l = __bfloat162float(__float2bfloat16(qk[i][j])) * SCALE + bbx[i][j] * SCALE;
                bool ok = (sg <= MM + tg) && (qi_s[qbase + i] == ki_s[sbase + j]);
                l = ok ? l : NEGINF;
                lv[i][j] = l;
                g_logits[((size_t)bn * TT + tg) * SS + sg] = l;
            }
        }
#pragma unroll
        for (int i = 0; i < 4; i++) {
            float tm = fmaxf(fmaxf(lv[i][0], lv[i][1]), fmaxf(lv[i][2], lv[i][3]));
#pragma unroll
            for (int msk = 1; msk < 16; msk <<= 1)
                tm = fmaxf(tm, __shfl_xor_sync(0xffffffffu, tm, msk));
            float nm = fmaxf(rmax[i], tm);
            float ps = expf(lv[i][0] - nm) + expf(lv[i][1] - nm) +
                       expf(lv[i][2] - nm) + expf(lv[i][3] - nm);
#pragma unroll
            for (int msk = 1; msk < 16; msk <<= 1)
                ps += __shfl_xor_sync(0xffffffffu, ps, msk);
            rsum[i] = rsum[i] * expf(rmax[i] - nm) + ps;
            rmax[i] = nm;
        }
    }
    if (tx == 0) {
#pragma unroll
        for (int i = 0; i < 4; i++) {
            rm_s[qbase + i] = rmax[i];
            rs_s[qbase + i] = rsum[i];
        }
    }
    __syncthreads();

    // ---------- phase 2: probs (bf16 after normalization) @ val ----------
    float* p_s = qu_s;
    float* v_s = qv_s;
    float acc[4][4];
#pragma unroll
    for (int i = 0; i < 4; i++)
#pragma unroll
        for (int j = 0; j < 4; j++) acc[i][j] = 0.f;

    for (int s0 = 0; s0 < SS; s0 += 64) {
        if (s0 > causal_max) break;
        {
            int klo = g_ki[b * SS + s0];
            int khi = g_ki[b * SS + s0 + 63];
            if (khi < qlo || klo > qhi) continue;
        }
        __syncthreads();
        for (int e = tid; e < 4096; e += 256) {
            int q = e >> 6, s = e & 63;
            float L = g_logits[((size_t)bn * TT + t0 + q) * SS + s0 + s];
            float p = expf(L - rm_s[q]) / rs_s[q];
            p_s[q * 65 + s] = __bfloat162float(__float2bfloat16(p));
        }
        for (int e = tid; e < 4096; e += 256) {
            int s = e >> 6, h = e & 63;
            v_s[s * 65 + h] = __bfloat162float(g_vb[(size_t)(b * SS + s0 + s) * NH + n * 64 + h]);
        }
        __syncthreads();
#pragma unroll 8
        for (int s = 0; s < 64; s++) {
            float pv[4], vv[4];
#pragma unroll
            for (int i = 0; i < 4; i++) pv[i] = p_s[(ty * 4 + i) * 65 + s];
#pragma unroll
            for (int j = 0; j < 4; j++) vv[j] = v_s[s * 65 + tx * 4 + j];
#pragma unroll
            for (int i = 0; i < 4; i++)
#pragma unroll
                for (int j = 0; j < 4; j++)
                    acc[i][j] = fmaf(pv[i], vv[j], acc[i][j]);
        }
    }
#pragma unroll
    for (int i = 0; i < 4; i++) {
        int t = t0 + ty * 4 + i;
#pragma unroll
        for (int j = 0; j < 4; j++) {
            g_attnb[(size_t)(b * TT + t) * NH + n * 64 + tx * 4 + j] =
                __float2bfloat16(acc[i][j]);
        }
    }
}

// ======================= launch =======================
extern "C" void kernel_launch(void* const* d_in, const int* in_sizes, int n_in,
                              void* d_out, int out_size)
{
    const float* x    = (const float*)d_in[0];
    const float* rel  = (const float*)d_in[1];
    const float* mem  = (const float*)d_in[2];
    const int*   ep   = (const int*)d_in[3];
    const int*   dones= (const int*)d_in[4];
    const float* Wq   = (const float*)d_in[5];
    const float* Wk   = (const float*)d_in[6];
    const float* Wv   = (const float*)d_in[7];
    const float* Wr   = (const float*)d_in[8];
    const float* u    = (const float*)d_in[9];
    const float* v    = (const float*)d_in[10];
    const float* Wout = (const float*)d_in[11];
    const float* bo   = (const float*)d_in[12];
    float* out = (float*)d_out;
    (void)in_sizes; (void)n_in; (void)out_size;

    // ---- all conversions + qi/ki in one launch ----
    prep<<<PREP_GRID, 256>>>(x, mem, rel, Wq, Wk, Wv, Wr, Wout, ep, dones);

    // ---- merged projection GEMMs (q, k, v, r) ----
    cudaFuncSetAttribute(proj_gemm, cudaFuncAttributeMaxDynamicSharedMemorySize, HG_SMEM);
    proj_gemm<<<dim3(8, 96), 256, HG_SMEM>>>(v, u);

    // ---- fused attention (tile-skipped, two-phase) ----
    const int att_smem = (3 * 64 * 65 + 128 * 65 + 128) * (int)sizeof(float) + 128 * (int)sizeof(int);
    cudaFuncSetAttribute(att_fused, cudaFuncAttributeMaxDynamicSharedMemorySize, att_smem);
    att_fused<<<dim3(BB * NHEAD, TT / 64), 256, att_smem>>>(ep);

    // ---- output projection ----
    cudaFuncSetAttribute(out_gemm, cudaFuncAttributeMaxDynamicSharedMemorySize, HG_SMEM);
    out_gemm<<<dim3(8, 16), 256, HG_SMEM>>>(bo, out);
}